// round 5
// baseline (speedup 1.0000x reference)
#include <cuda_runtime.h>
#include <cuda_bf16.h>
#include <cstdint>
#include <cstdio>

// Problem constants
#define BB 2
#define SS 2048
#define EE 1024
#define RR 256
#define HH 16
#define DD 64          // head dim (v); qk head dim = 128
#define MM (BB*SS)     // 4096

// ---------------- scratch (device globals; no allocation allowed) ----------
__device__ float g_qlat[MM*RR];
__device__ float g_klat[MM*RR];
__device__ float g_kv  [MM*RR];
__device__ float g_qr  [MM*EE];
__device__ float g_qn  [MM*EE];
__device__ float g_kr  [MM*EE];
__device__ float g_kn  [MM*EE];
__device__ float g_vf  [MM*EE];
__device__ float g_q   [BB*HH*SS*128];
__device__ float g_k   [BB*HH*SS*128];
__device__ float g_v   [BB*HH*SS*64];
__device__ float g_y   [MM*EE];

// ---------------- SGEMM: C[M,N] = A[M,K] * W[N,K]^T  (all row-major) -------
template<int BM, int BN, int BK, int TM, int TN>
__global__ void __launch_bounds__(256) sgemm_nt(
    const float* __restrict__ A, const float* __restrict__ W,
    float* __restrict__ C, int M, int N, int K)
{
    constexpr int PAD = 4;
    constexpr int NT  = (BM/TM)*(BN/TN);   // must be 256
    static_assert(NT == 256, "thread count");
    __shared__ __align__(16) float As[BK*(BM+PAD)];
    __shared__ __align__(16) float Ws[BK*(BN+PAD)];

    const int tid = threadIdx.x;
    const int tx  = tid % (BN/TN);
    const int ty  = tid / (BN/TN);
    const int m0  = blockIdx.y * BM;
    const int n0  = blockIdx.x * BN;

    float acc[TM][TN];
    #pragma unroll
    for (int i = 0; i < TM; i++)
        #pragma unroll
        for (int j = 0; j < TN; j++) acc[i][j] = 0.f;

    constexpr int KV = BK/4;
    for (int kt = 0; kt < K; kt += BK) {
        #pragma unroll
        for (int idx = tid; idx < BM*KV; idx += NT) {
            int row = idx / KV, kq = idx % KV;
            float4 v = *(const float4*)(A + (size_t)(m0+row)*K + kt + kq*4);
            As[(kq*4+0)*(BM+PAD)+row] = v.x;
            As[(kq*4+1)*(BM+PAD)+row] = v.y;
            As[(kq*4+2)*(BM+PAD)+row] = v.z;
            As[(kq*4+3)*(BM+PAD)+row] = v.w;
        }
        #pragma unroll
        for (int idx = tid; idx < BN*KV; idx += NT) {
            int row = idx / KV, kq = idx % KV;
            float4 v = *(const float4*)(W + (size_t)(n0+row)*K + kt + kq*4);
            Ws[(kq*4+0)*(BN+PAD)+row] = v.x;
            Ws[(kq*4+1)*(BN+PAD)+row] = v.y;
            Ws[(kq*4+2)*(BN+PAD)+row] = v.z;
            Ws[(kq*4+3)*(BN+PAD)+row] = v.w;
        }
        __syncthreads();
        #pragma unroll
        for (int k = 0; k < BK; k++) {
            float a[TM], b[TN];
            #pragma unroll
            for (int i = 0; i < TM; i++) a[i] = As[k*(BM+PAD) + ty*TM + i];
            #pragma unroll
            for (int j = 0; j < TN; j++) b[j] = Ws[k*(BN+PAD) + tx*TN + j];
            #pragma unroll
            for (int i = 0; i < TM; i++)
                #pragma unroll
                for (int j = 0; j < TN; j++)
                    acc[i][j] = fmaf(a[i], b[j], acc[i][j]);
        }
        __syncthreads();
    }

    #pragma unroll
    for (int i = 0; i < TM; i++) {
        #pragma unroll
        for (int j0 = 0; j0 < TN; j0 += 4) {
            float4 o;
            o.x = acc[i][j0+0]; o.y = acc[i][j0+1];
            o.z = acc[i][j0+2]; o.w = acc[i][j0+3];
            *(float4*)(C + (size_t)(m0+ty*TM+i)*N + n0 + tx*TN + j0) = o;
        }
    }
}

// --------- build q/k: rope(heads(rope_in)) || heads(up_in) -> [B,H,S,128] --
__global__ void build_qk_kernel(const float* __restrict__ ropein,
                                const float* __restrict__ upin,
                                float* __restrict__ outp)
{
    int idx = blockIdx.x * blockDim.x + threadIdx.x;   // over B*H*S*64
    if (idx >= BB*HH*SS*64) return;
    int d = idx & 63;
    int s = (idx >> 6) & (SS-1);
    int h = (idx >> 17) & (HH-1);
    int b = idx >> 21;
    const int base_in = (b*SS + s)*EE + h*64;
    float x1 = ropein[base_in + d];
    float rot; int fi;
    if (d < 32) { rot = -ropein[base_in + d + 32]; fi = d; }
    else        { rot =  ropein[base_in + d - 32]; fi = d - 32; }
    float inv = __powf(10000.0f, -(float)(2*fi) * (1.0f/64.0f));
    float ang = (float)s * inv;
    float sn, cs; sincosf(ang, &sn, &cs);
    float val = fmaf(x1, cs, rot*sn);
    const int ob = ((b*HH + h)*SS + s)*128;
    outp[ob + d]      = val;
    outp[ob + 64 + d] = upin[base_in + d];
}

// --------- build v: heads(v_full) -> [B,H,S,64] ----------------------------
__global__ void build_v_kernel(const float* __restrict__ vf, float* __restrict__ vout)
{
    int idx = blockIdx.x * blockDim.x + threadIdx.x;   // over B*H*S*64
    if (idx >= BB*HH*SS*64) return;
    int d = idx & 63;
    int s = (idx >> 6) & (SS-1);
    int h = (idx >> 17) & (HH-1);
    int b = idx >> 21;
    vout[idx] = vf[(b*SS + s)*EE + h*64 + d];
}

// ---------------- causal flash attention (fp32) ----------------------------
// Q,K: [B,H,S,128], V: [B,H,S,64] -> Y: [B,S,E] (= [B,S,H*64])
// block: 64 q-rows for one (b,h); 256 threads (16x16), 4x4 microtiles
#define QK_STRIDE 68
__global__ void __launch_bounds__(256) attn_kernel(
    const float* __restrict__ Q, const float* __restrict__ Kg,
    const float* __restrict__ Vg, float* __restrict__ Y)
{
    extern __shared__ __align__(16) float sm[];
    float* Qt = sm;                          // [128][68] transposed: Qt[d][row]
    float* Kt = Qt + 128*QK_STRIDE;          // [128][68]
    float* Vs = Kt + 128*QK_STRIDE;          // [64][68]  Vs[row][d]
    float* Pt = Vs + 64*QK_STRIDE;           // [64][68]  Pt[kcol][qrow]

    const int tid = threadIdx.x;
    const int tx = tid & 15, ty = tid >> 4;
    const int q0 = blockIdx.x * 64;
    const int bh = blockIdx.y;               // b*H + h
    const int b  = bh >> 4, h = bh & 15;
    const float scale = 0.08838834764831845f; // 1/sqrt(128)

    // load Q tile once (transposed, pre-scaled)
    const float* qbase = Q + ((size_t)bh * SS + q0) * 128;
    for (int idx = tid; idx < 64*32; idx += 256) {
        int row = idx >> 5, d4 = idx & 31;
        float4 v = *(const float4*)(qbase + row*128 + d4*4);
        Qt[(d4*4+0)*QK_STRIDE + row] = v.x * scale;
        Qt[(d4*4+1)*QK_STRIDE + row] = v.y * scale;
        Qt[(d4*4+2)*QK_STRIDE + row] = v.z * scale;
        Qt[(d4*4+3)*QK_STRIDE + row] = v.w * scale;
    }

    float m_i[4], l_i[4], acc[4][4];
    #pragma unroll
    for (int i = 0; i < 4; i++) {
        m_i[i] = -1e30f; l_i[i] = 0.f;
        #pragma unroll
        for (int j = 0; j < 4; j++) acc[i][j] = 0.f;
    }

    const float* kbase = Kg + (size_t)bh * SS * 128;
    const float* vbase = Vg + (size_t)bh * SS * 64;

    for (int k0 = 0; k0 <= q0; k0 += 64) {
        __syncthreads();   // previous iteration done reading Kt/Vs/Pt
        for (int idx = tid; idx < 64*32; idx += 256) {
            int row = idx >> 5, d4 = idx & 31;
            float4 v = *(const float4*)(kbase + (size_t)(k0+row)*128 + d4*4);
            Kt[(d4*4+0)*QK_STRIDE + row] = v.x;
            Kt[(d4*4+1)*QK_STRIDE + row] = v.y;
            Kt[(d4*4+2)*QK_STRIDE + row] = v.z;
            Kt[(d4*4+3)*QK_STRIDE + row] = v.w;
        }
        for (int idx = tid; idx < 64*16; idx += 256) {
            int row = idx >> 4, d4 = idx & 15;
            float4 v = *(const float4*)(vbase + (size_t)(k0+row)*64 + d4*4);
            *(float4*)(Vs + row*QK_STRIDE + d4*4) = v;
        }
        __syncthreads();

        // S = (Q*scale) @ K^T : 64x64, each thread 4x4
        float s[4][4];
        #pragma unroll
        for (int i = 0; i < 4; i++)
            #pragma unroll
            for (int j = 0; j < 4; j++) s[i][j] = 0.f;
        #pragma unroll 4
        for (int d = 0; d < 128; d++) {
            float4 a4 = *(const float4*)(Qt + d*QK_STRIDE + ty*4);
            float4 b4 = *(const float4*)(Kt + d*QK_STRIDE + tx*4);
            float a[4] = {a4.x, a4.y, a4.z, a4.w};
            float bb2[4] = {b4.x, b4.y, b4.z, b4.w};
            #pragma unroll
            for (int i = 0; i < 4; i++)
                #pragma unroll
                for (int j = 0; j < 4; j++)
                    s[i][j] = fmaf(a[i], bb2[j], s[i][j]);
        }

        // causal mask (only on the diagonal tile)
        if (k0 == q0) {
            #pragma unroll
            for (int i = 0; i < 4; i++)
                #pragma unroll
                for (int j = 0; j < 4; j++)
                    if (tx*4 + j > ty*4 + i) s[i][j] = -1e30f;
        }

        // online softmax update
        #pragma unroll
        for (int i = 0; i < 4; i++) {
            float rmax = fmaxf(fmaxf(s[i][0], s[i][1]), fmaxf(s[i][2], s[i][3]));
            #pragma unroll
            for (int off = 8; off >= 1; off >>= 1)
                rmax = fmaxf(rmax, __shfl_xor_sync(0xffffffffu, rmax, off));
            float mnew  = fmaxf(m_i[i], rmax);
            float alpha = __expf(m_i[i] - mnew);
            float rsum = 0.f;
            #pragma unroll
            for (int j = 0; j < 4; j++) {
                s[i][j] = __expf(s[i][j] - mnew);
                rsum += s[i][j];
            }
            #pragma unroll
            for (int off = 8; off >= 1; off >>= 1)
                rsum += __shfl_xor_sync(0xffffffffu, rsum, off);
            l_i[i] = l_i[i] * alpha + rsum;
            m_i[i] = mnew;
            #pragma unroll
            for (int j = 0; j < 4; j++) acc[i][j] *= alpha;
        }

        // write P transposed: Pt[kcol][qrow]
        #pragma unroll
        for (int i = 0; i < 4; i++)
            #pragma unroll
            for (int j = 0; j < 4; j++)
                Pt[(tx*4+j)*QK_STRIDE + ty*4 + i] = s[i][j];
        __syncthreads();

        // O += P @ V
        #pragma unroll 4
        for (int kk = 0; kk < 64; kk++) {
            float4 a4 = *(const float4*)(Pt + kk*QK_STRIDE + ty*4);
            float4 b4 = *(const float4*)(Vs + kk*QK_STRIDE + tx*4);
            float a[4] = {a4.x, a4.y, a4.z, a4.w};
            float bb2[4] = {b4.x, b4.y, b4.z, b4.w};
            #pragma unroll
            for (int i = 0; i < 4; i++)
                #pragma unroll
                for (int j = 0; j < 4; j++)
                    acc[i][j] = fmaf(a[i], bb2[j], acc[i][j]);
        }
    }

    // write Y[b, q, h*64 + d]
    #pragma unroll
    for (int i = 0; i < 4; i++) {
        float inv = 1.0f / l_i[i];
        int row = q0 + ty*4 + i;
        float4 o;
        o.x = acc[i][0]*inv; o.y = acc[i][1]*inv;
        o.z = acc[i][2]*inv; o.w = acc[i][3]*inv;
        *(float4*)(Y + ((size_t)b*SS + row)*EE + h*64 + tx*4) = o;
    }
}

#define ATTN_SMEM ((128*QK_STRIDE*2 + 64*QK_STRIDE*2) * sizeof(float))

// ---------------- host launcher --------------------------------------------
extern "C" void kernel_launch(void* const* d_in, const int* in_sizes, int n_in,
                              void* d_out, int out_size)
{
    const float* x       = (const float*)d_in[0];
    const float* wq_down = (const float*)d_in[1];
    const float* wk_rope = (const float*)d_in[2];
    const float* wkv_down= (const float*)d_in[3];
    const float* wq_rope = (const float*)d_in[4];
    const float* wq_up   = (const float*)d_in[5];
    const float* wk_up   = (const float*)d_in[6];
    const float* wv_up   = (const float*)d_in[7];
    const float* wo      = (const float*)d_in[8];
    float* out = (float*)d_out;

    static float *p_qlat=nullptr,*p_klat=nullptr,*p_kv=nullptr,
                 *p_qr=nullptr,*p_qn=nullptr,*p_kr=nullptr,*p_kn=nullptr,*p_vf=nullptr,
                 *p_q=nullptr,*p_k=nullptr,*p_v=nullptr,*p_y=nullptr;
    static bool inited = false;
    if (!inited) {
        cudaGetSymbolAddress((void**)&p_qlat, g_qlat);
        cudaGetSymbolAddress((void**)&p_klat, g_klat);
        cudaGetSymbolAddress((void**)&p_kv,   g_kv);
        cudaGetSymbolAddress((void**)&p_qr,   g_qr);
        cudaGetSymbolAddress((void**)&p_qn,   g_qn);
        cudaGetSymbolAddress((void**)&p_kr,   g_kr);
        cudaGetSymbolAddress((void**)&p_kn,   g_kn);
        cudaGetSymbolAddress((void**)&p_vf,   g_vf);
        cudaGetSymbolAddress((void**)&p_q,    g_q);
        cudaGetSymbolAddress((void**)&p_k,    g_k);
        cudaGetSymbolAddress((void**)&p_v,    g_v);
        cudaGetSymbolAddress((void**)&p_y,    g_y);
        cudaFuncSetAttribute(attn_kernel,
                             cudaFuncAttributeMaxDynamicSharedMemorySize,
                             (int)ATTN_SMEM);
        inited = true;
    }

    // stage 1: down projections (M=4096, N=256, K=1024)
    dim3 g1(RR/64, MM/64);
    sgemm_nt<64,64,16,4,4><<<g1, 256>>>(x, wq_down,  p_qlat, MM, RR, EE);
    sgemm_nt<64,64,16,4,4><<<g1, 256>>>(x, wk_rope,  p_klat, MM, RR, EE);
    sgemm_nt<64,64,16,4,4><<<g1, 256>>>(x, wkv_down, p_kv,   MM, RR, EE);

    // stage 2: up projections (M=4096, N=1024, K=256)
    dim3 g2(EE/128, MM/128);
    sgemm_nt<128,128,16,8,8><<<g2, 256>>>(p_qlat, wq_rope, p_qr, MM, EE, RR);
    sgemm_nt<128,128,16,8,8><<<g2, 256>>>(p_qlat, wq_up,   p_qn, MM, EE, RR);
    sgemm_nt<128,128,16,8,8><<<g2, 256>>>(p_klat, wk_up,   p_kr, MM, EE, RR);
    sgemm_nt<128,128,16,8,8><<<g2, 256>>>(p_kv,   wk_up,   p_kn, MM, EE, RR);
    sgemm_nt<128,128,16,8,8><<<g2, 256>>>(p_kv,   wv_up,   p_vf, MM, EE, RR);

    // stage 3: head layout + RoPE
    int nb = (BB*HH*SS*64 + 255) / 256;
    build_qk_kernel<<<nb, 256>>>(p_qr, p_qn, p_q);
    build_qk_kernel<<<nb, 256>>>(p_kr, p_kn, p_k);
    build_v_kernel<<<nb, 256>>>(p_vf, p_v);

    // stage 4: causal flash attention
    attn_kernel<<<dim3(SS/64, BB*HH), 256, ATTN_SMEM>>>(p_q, p_k, p_v, p_y);

    // stage 5: output projection (M=4096, N=1024, K=1024)
    sgemm_nt<128,128,16,8,8><<<g2, 256>>>(p_y, wo, out, MM, EE, EE);
}

// round 6
// speedup vs baseline: 2.1783x; 2.1783x over previous
#include <cuda_runtime.h>
#include <cuda_bf16.h>
#include <cstdint>

// Problem constants
#define BB 2
#define SS 2048
#define EE 1024
#define RR 256
#define HH 16
#define MM (BB*SS)     // 4096

// ---------------- scratch (device globals; no allocation allowed) ----------
__device__ float g_qlat[MM*RR];
__device__ float g_klat[MM*RR];
__device__ float g_kv  [MM*RR];
__device__ float g_qr  [MM*EE];
__device__ float g_qn  [MM*EE];
__device__ float g_kr  [MM*EE];
__device__ float g_kn  [MM*EE];
__device__ float g_vf  [MM*EE];
__device__ float g_q   [BB*HH*SS*128];
__device__ float g_k   [BB*HH*SS*128];
__device__ float g_v   [BB*HH*SS*64];
__device__ float g_y   [MM*EE];

// ---------------- tf32 helpers ---------------------------------------------
__device__ __forceinline__ uint32_t tf32u(float x) {
    uint32_t r; asm("cvt.rna.tf32.f32 %0, %1;" : "=r"(r) : "f"(x)); return r;
}
__device__ __forceinline__ float tf32f(float x) {
    return __uint_as_float(tf32u(x));
}
// D += A(16x8,row) * B(8x8,col), tf32 inputs, fp32 accumulate
__device__ __forceinline__ void mma_tf32(float4& c, const uint32_t* a, const uint32_t* b) {
    asm volatile("mma.sync.aligned.m16n8k8.row.col.f32.tf32.tf32.f32 "
        "{%0,%1,%2,%3}, {%4,%5,%6,%7}, {%8,%9}, {%0,%1,%2,%3};\n"
        : "+f"(c.x), "+f"(c.y), "+f"(c.z), "+f"(c.w)
        : "r"(a[0]), "r"(a[1]), "r"(a[2]), "r"(a[3]), "r"(b[0]), "r"(b[1]));
}

// ---------------- tf32 tensor-core GEMM: C[M,N] = A[M,K] * W[N,K]^T --------
// 256 threads = 8 warps; warp grid (BM/WM) x (BN/WN) must be 8.
template<int BM, int BN, int BK, int WM, int WN>
__global__ void __launch_bounds__(256) mma_gemm(
    const float* __restrict__ A, const float* __restrict__ W,
    float* __restrict__ C, int M, int N, int K)
{
    constexpr int BKP = BK + 4;
    constexpr int WARPS_N = BN / WN;
    constexpr int MT  = WM / 16;
    constexpr int NT2 = WN / 8;
    static_assert((BM/WM) * (BN/WN) == 8, "warp grid");
    __shared__ __align__(16) uint32_t As[BM*BKP];
    __shared__ __align__(16) uint32_t Ws[BN*BKP];

    const int tid  = threadIdx.x;
    const int wid  = tid >> 5, lane = tid & 31;
    const int g    = lane >> 2, t4 = lane & 3;
    const int wr   = wid / WARPS_N, wc = wid % WARPS_N;
    const int m0w  = wr * WM, n0w = wc * WN;
    const int m0   = blockIdx.y * BM;
    const int n0   = blockIdx.x * BN;

    float4 acc[MT][NT2];
    #pragma unroll
    for (int m = 0; m < MT; m++)
        #pragma unroll
        for (int n = 0; n < NT2; n++) acc[m][n] = make_float4(0.f,0.f,0.f,0.f);

    for (int kt = 0; kt < K; kt += BK) {
        #pragma unroll
        for (int idx = tid; idx < BM*BK/4; idx += 256) {
            int row = idx / (BK/4), seg = idx % (BK/4);
            float4 v = *(const float4*)(A + (size_t)(m0+row)*K + kt + seg*4);
            uint32_t* p = As + row*BKP + seg*4;
            p[0]=tf32u(v.x); p[1]=tf32u(v.y); p[2]=tf32u(v.z); p[3]=tf32u(v.w);
        }
        #pragma unroll
        for (int idx = tid; idx < BN*BK/4; idx += 256) {
            int row = idx / (BK/4), seg = idx % (BK/4);
            float4 v = *(const float4*)(W + (size_t)(n0+row)*K + kt + seg*4);
            uint32_t* p = Ws + row*BKP + seg*4;
            p[0]=tf32u(v.x); p[1]=tf32u(v.y); p[2]=tf32u(v.z); p[3]=tf32u(v.w);
        }
        __syncthreads();

        #pragma unroll
        for (int k8 = 0; k8 < BK; k8 += 8) {
            uint32_t bf[NT2][2];
            #pragma unroll
            for (int n = 0; n < NT2; n++) {
                const uint32_t* bp = Ws + (n0w + n*8 + g)*BKP + k8 + t4;
                bf[n][0] = bp[0];
                bf[n][1] = bp[4];
            }
            #pragma unroll
            for (int m = 0; m < MT; m++) {
                const uint32_t* ap = As + (m0w + m*16 + g)*BKP + k8 + t4;
                uint32_t af[4] = { ap[0], ap[8*BKP], ap[4], ap[8*BKP + 4] };
                #pragma unroll
                for (int n = 0; n < NT2; n++)
                    mma_tf32(acc[m][n], af, bf[n]);
            }
        }
        __syncthreads();
    }

    #pragma unroll
    for (int m = 0; m < MT; m++) {
        #pragma unroll
        for (int n = 0; n < NT2; n++) {
            int row = m0 + m0w + m*16 + g;
            int col = n0 + n0w + n*8 + 2*t4;
            *(float2*)(C + (size_t)row*N + col)     = make_float2(acc[m][n].x, acc[m][n].y);
            *(float2*)(C + (size_t)(row+8)*N + col) = make_float2(acc[m][n].z, acc[m][n].w);
        }
    }
}

// --------- build q/k: rope(heads(rope_in)) || heads(up_in) -> [B,H,S,128] --
// Output is pre-rounded to tf32; `scale` is folded in (1/sqrt(128) for q).
__global__ void build_qk_kernel(const float* __restrict__ ropein,
                                const float* __restrict__ upin,
                                float* __restrict__ outp, float scale)
{
    int idx = blockIdx.x * blockDim.x + threadIdx.x;   // over B*H*S*64
    if (idx >= BB*HH*SS*64) return;
    int d = idx & 63;
    int s = (idx >> 6) & (SS-1);
    int h = (idx >> 17) & (HH-1);
    int b = idx >> 21;
    const int base_in = (b*SS + s)*EE + h*64;
    float x1 = ropein[base_in + d];
    float rot; int fi;
    if (d < 32) { rot = -ropein[base_in + d + 32]; fi = d; }
    else        { rot =  ropein[base_in + d - 32]; fi = d - 32; }
    float inv = __powf(10000.0f, -(float)(2*fi) * (1.0f/64.0f));
    float ang = (float)s * inv;
    float sn, cs; sincosf(ang, &sn, &cs);
    float val = fmaf(x1, cs, rot*sn);
    const int ob = ((b*HH + h)*SS + s)*128;
    outp[ob + d]      = tf32f(val * scale);
    outp[ob + 64 + d] = tf32f(upin[base_in + d] * scale);
}

// --------- build v: heads(v_full) -> [B,H,S,64], tf32-rounded --------------
__global__ void build_v_kernel(const float* __restrict__ vf, float* __restrict__ vout)
{
    int idx = blockIdx.x * blockDim.x + threadIdx.x;   // over B*H*S*64
    if (idx >= BB*HH*SS*64) return;
    int d = idx & 63;
    int s = (idx >> 6) & (SS-1);
    int h = (idx >> 17) & (HH-1);
    int b = idx >> 21;
    vout[idx] = tf32f(vf[(b*SS + s)*EE + h*64 + d]);
}

// ---------------- causal flash attention, tf32 tensor cores ----------------
// Q,K: [B,H,S,128] (tf32 bits, Q pre-scaled), V: [B,H,S,64] (tf32 bits)
// -> Y: [B,S,E]. One CTA: 128 q-rows for one (b,h). 256 threads = 8 warps,
// warp grid 4(row)x2(col), 32x32 warp tiles for both S and O.
#define ATQ 128
#define ATK 64
#define QSTR 136   // 128 + 8 : (g*136 + t4) % 32 = 8g + t4, conflict-free
#define SSTR 72    // 64 + 8  : 8g+t4 / 8t4+g, conflict-free

__global__ void __launch_bounds__(256) attn_mma(
    const float* __restrict__ Q, const float* __restrict__ Kg,
    const float* __restrict__ Vg, float* __restrict__ Y)
{
    extern __shared__ __align__(16) uint32_t smu[];
    uint32_t* Qs  = smu;                    // [ATQ][QSTR]
    uint32_t* Ks  = Qs + ATQ*QSTR;          // [ATK][QSTR]
    uint32_t* Vs  = Ks + ATK*QSTR;          // [ATK][SSTR]  (Vs[k][d])
    uint32_t* Ssu = Vs + ATK*SSTR;          // [ATQ][SSTR]  scores / P
    float*    Ss  = (float*)Ssu;
    float*    msm = (float*)(Ssu + ATQ*SSTR);
    float*    lsm = msm + ATQ;
    float*    alph= lsm + ATQ;

    const int tid = threadIdx.x;
    const int lane = tid & 31, wid = tid >> 5;
    const int g = lane >> 2, t4 = lane & 3;
    const int wrs = wid >> 1, wcs = wid & 1;
    const int q0 = ((int)gridDim.x - 1 - (int)blockIdx.x) * ATQ;  // heavy tiles first
    const int bh = blockIdx.y, b = bh >> 4, h = bh & 15;

    // stage Q once (values already tf32 bits + scaled)
    const float* qbase = Q + ((size_t)bh*SS + q0)*128;
    for (int idx = tid; idx < ATQ*32; idx += 256) {
        int row = idx >> 5, seg = idx & 31;
        float4 v = *(const float4*)(qbase + row*128 + seg*4);
        *(float4*)((float*)Qs + row*QSTR + seg*4) = v;
    }
    if (tid < ATQ) { msm[tid] = -1e30f; lsm[tid] = 0.f; }

    float4 oacc[2][4];
    #pragma unroll
    for (int m = 0; m < 2; m++)
        #pragma unroll
        for (int n = 0; n < 4; n++) oacc[m][n] = make_float4(0.f,0.f,0.f,0.f);

    const float* kbase = Kg + (size_t)bh*SS*128;
    const float* vbase = Vg + (size_t)bh*SS*64;

    for (int k0 = 0; k0 <= q0 + (ATQ - ATK); k0 += ATK) {
        __syncthreads();   // previous iteration done with Ks/Vs/Ss
        for (int idx = tid; idx < ATK*32; idx += 256) {
            int row = idx >> 5, seg = idx & 31;
            float4 v = *(const float4*)(kbase + (size_t)(k0+row)*128 + seg*4);
            *(float4*)((float*)Ks + row*QSTR + seg*4) = v;
        }
        for (int idx = tid; idx < ATK*16; idx += 256) {
            int row = idx >> 4, seg = idx & 15;
            float4 v = *(const float4*)(vbase + (size_t)(k0+row)*64 + seg*4);
            *(float4*)((float*)Vs + row*SSTR + seg*4) = v;
        }
        __syncthreads();

        // ---- S = Q @ K^T (128x64), warp tile 32x32 ----
        float4 sf[2][4];
        #pragma unroll
        for (int m = 0; m < 2; m++)
            #pragma unroll
            for (int n = 0; n < 4; n++) sf[m][n] = make_float4(0.f,0.f,0.f,0.f);

        #pragma unroll
        for (int d8 = 0; d8 < 128; d8 += 8) {
            uint32_t bf[4][2];
            #pragma unroll
            for (int n = 0; n < 4; n++) {
                const uint32_t* bp = Ks + (wcs*32 + n*8 + g)*QSTR + d8 + t4;
                bf[n][0] = bp[0];
                bf[n][1] = bp[4];
            }
            #pragma unroll
            for (int m = 0; m < 2; m++) {
                const uint32_t* ap = Qs + (wrs*32 + m*16 + g)*QSTR + d8 + t4;
                uint32_t af[4] = { ap[0], ap[8*QSTR], ap[4], ap[8*QSTR + 4] };
                #pragma unroll
                for (int n = 0; n < 4; n++) mma_tf32(sf[m][n], af, bf[n]);
            }
        }

        // ---- mask + store scores ----
        const bool need_mask = (k0 + ATK - 1 > q0);
        #pragma unroll
        for (int m = 0; m < 2; m++) {
            int lr = wrs*32 + m*16 + g;
            #pragma unroll
            for (int n = 0; n < 4; n++) {
                int lc = wcs*32 + n*8 + 2*t4;
                float4 v = sf[m][n];
                if (need_mask) {
                    int qr = q0 + lr, kc = k0 + lc;
                    if (kc     > qr)     v.x = -1e30f;
                    if (kc + 1 > qr)     v.y = -1e30f;
                    if (kc     > qr + 8) v.z = -1e30f;
                    if (kc + 1 > qr + 8) v.w = -1e30f;
                }
                *(float2*)(Ss + lr*SSTR + lc)     = make_float2(v.x, v.y);
                *(float2*)(Ss + (lr+8)*SSTR + lc) = make_float2(v.z, v.w);
            }
        }
        __syncthreads();

        // ---- online softmax: 2 threads per row, 32 cols each ----
        {
            int r = tid >> 1, half = tid & 1;
            float* rowp = Ss + r*SSTR + half*32;
            float4 vv[8];
            #pragma unroll
            for (int i = 0; i < 8; i++) vv[i] = *(float4*)(rowp + i*4);
            float mx = -1e30f;
            #pragma unroll
            for (int i = 0; i < 8; i++)
                mx = fmaxf(mx, fmaxf(fmaxf(vv[i].x, vv[i].y), fmaxf(vv[i].z, vv[i].w)));
            mx = fmaxf(mx, __shfl_xor_sync(0xffffffffu, mx, 1));
            float m_old = msm[r];
            float m_new = fmaxf(m_old, mx);
            float alpha = __expf(m_old - m_new);
            float sum = 0.f;
            #pragma unroll
            for (int i = 0; i < 8; i++) {
                vv[i].x = __expf(vv[i].x - m_new); sum += vv[i].x;
                vv[i].y = __expf(vv[i].y - m_new); sum += vv[i].y;
                vv[i].z = __expf(vv[i].z - m_new); sum += vv[i].z;
                vv[i].w = __expf(vv[i].w - m_new); sum += vv[i].w;
            }
            sum += __shfl_xor_sync(0xffffffffu, sum, 1);
            if (half == 0) {
                msm[r]  = m_new;
                lsm[r]  = lsm[r]*alpha + sum;
                alph[r] = alpha;
            }
            #pragma unroll
            for (int i = 0; i < 8; i++) {
                float4 t;
                t.x = tf32f(vv[i].x); t.y = tf32f(vv[i].y);
                t.z = tf32f(vv[i].z); t.w = tf32f(vv[i].w);
                *(float4*)(rowp + i*4) = t;
            }
        }
        __syncthreads();

        // ---- O = O*alpha + P @ V, warp tile 32x32 ----
        #pragma unroll
        for (int m = 0; m < 2; m++) {
            int lr = wrs*32 + m*16 + g;
            float alo = alph[lr], ahi = alph[lr+8];
            #pragma unroll
            for (int n = 0; n < 4; n++) {
                oacc[m][n].x *= alo; oacc[m][n].y *= alo;
                oacc[m][n].z *= ahi; oacc[m][n].w *= ahi;
            }
        }
        #pragma unroll
        for (int k8 = 0; k8 < ATK; k8 += 8) {
            uint32_t bf[4][2];
            #pragma unroll
            for (int n = 0; n < 4; n++) {
                const uint32_t* bp = Vs + (k8 + t4)*SSTR + wcs*32 + n*8 + g;
                bf[n][0] = bp[0];
                bf[n][1] = bp[4*SSTR];
            }
            #pragma unroll
            for (int m = 0; m < 2; m++) {
                const uint32_t* ap = Ssu + (wrs*32 + m*16 + g)*SSTR + k8 + t4;
                uint32_t af[4] = { ap[0], ap[8*SSTR], ap[4], ap[8*SSTR + 4] };
                #pragma unroll
                for (int n = 0; n < 4; n++) mma_tf32(oacc[m][n], af, bf[n]);
            }
        }
    }

    // ---- normalize + write Y[b, q, h*64 + d] ----
    #pragma unroll
    for (int m = 0; m < 2; m++) {
        int lr = wrs*32 + m*16 + g;
        float ilo = 1.f / lsm[lr], ihi = 1.f / lsm[lr+8];
        #pragma unroll
        for (int n = 0; n < 4; n++) {
            int lc = wcs*32 + n*8 + 2*t4;
            float* yp  = Y + ((size_t)b*SS + q0 + lr)*EE + h*64 + lc;
            *(float2*)yp  = make_float2(oacc[m][n].x*ilo, oacc[m][n].y*ilo);
            float* yp2 = Y + ((size_t)b*SS + q0 + lr + 8)*EE + h*64 + lc;
            *(float2*)yp2 = make_float2(oacc[m][n].z*ihi, oacc[m][n].w*ihi);
        }
    }
}

#define ATTN_SMEM ((ATQ*QSTR + ATK*QSTR + ATK*SSTR + ATQ*SSTR + 3*ATQ) * 4)

// ---------------- host launcher --------------------------------------------
extern "C" void kernel_launch(void* const* d_in, const int* in_sizes, int n_in,
                              void* d_out, int out_size)
{
    const float* x       = (const float*)d_in[0];
    const float* wq_down = (const float*)d_in[1];
    const float* wk_rope = (const float*)d_in[2];
    const float* wkv_down= (const float*)d_in[3];
    const float* wq_rope = (const float*)d_in[4];
    const float* wq_up   = (const float*)d_in[5];
    const float* wk_up   = (const float*)d_in[6];
    const float* wv_up   = (const float*)d_in[7];
    const float* wo      = (const float*)d_in[8];
    float* out = (float*)d_out;

    static float *p_qlat=nullptr,*p_klat=nullptr,*p_kv=nullptr,
                 *p_qr=nullptr,*p_qn=nullptr,*p_kr=nullptr,*p_kn=nullptr,*p_vf=nullptr,
                 *p_q=nullptr,*p_k=nullptr,*p_v=nullptr,*p_y=nullptr;
    static bool inited = false;
    if (!inited) {
        cudaGetSymbolAddress((void**)&p_qlat, g_qlat);
        cudaGetSymbolAddress((void**)&p_klat, g_klat);
        cudaGetSymbolAddress((void**)&p_kv,   g_kv);
        cudaGetSymbolAddress((void**)&p_qr,   g_qr);
        cudaGetSymbolAddress((void**)&p_qn,   g_qn);
        cudaGetSymbolAddress((void**)&p_kr,   g_kr);
        cudaGetSymbolAddress((void**)&p_kn,   g_kn);
        cudaGetSymbolAddress((void**)&p_vf,   g_vf);
        cudaGetSymbolAddress((void**)&p_q,    g_q);
        cudaGetSymbolAddress((void**)&p_k,    g_k);
        cudaGetSymbolAddress((void**)&p_v,    g_v);
        cudaGetSymbolAddress((void**)&p_y,    g_y);
        cudaFuncSetAttribute(attn_mma,
                             cudaFuncAttributeMaxDynamicSharedMemorySize,
                             (int)ATTN_SMEM);
        inited = true;
    }

    // stage 1: down projections (M=4096, N=256, K=1024), tf32 mma
    dim3 g1(RR/64, MM/128);
    mma_gemm<128,64,32,32,32><<<g1, 256>>>(x, wq_down,  p_qlat, MM, RR, EE);
    mma_gemm<128,64,32,32,32><<<g1, 256>>>(x, wk_rope,  p_klat, MM, RR, EE);
    mma_gemm<128,64,32,32,32><<<g1, 256>>>(x, wkv_down, p_kv,   MM, RR, EE);

    // stage 2: up projections (M=4096, N=1024, K=256), tf32 mma
    dim3 g2(EE/128, MM/128);
    mma_gemm<128,128,32,64,32><<<g2, 256>>>(p_qlat, wq_rope, p_qr, MM, EE, RR);
    mma_gemm<128,128,32,64,32><<<g2, 256>>>(p_qlat, wq_up,   p_qn, MM, EE, RR);
    mma_gemm<128,128,32,64,32><<<g2, 256>>>(p_klat, wk_up,   p_kr, MM, EE, RR);
    mma_gemm<128,128,32,64,32><<<g2, 256>>>(p_kv,   wk_up,   p_kn, MM, EE, RR);
    mma_gemm<128,128,32,64,32><<<g2, 256>>>(p_kv,   wv_up,   p_vf, MM, EE, RR);

    // stage 3: head layout + RoPE (tf32-rounded; q pre-scaled by 1/sqrt(128))
    int nb = (BB*HH*SS*64 + 255) / 256;
    build_qk_kernel<<<nb, 256>>>(p_qr, p_qn, p_q, 0.08838834764831845f);
    build_qk_kernel<<<nb, 256>>>(p_kr, p_kn, p_k, 1.0f);
    build_v_kernel<<<nb, 256>>>(p_vf, p_v);

    // stage 4: causal flash attention on tensor cores
    attn_mma<<<dim3(SS/ATQ, BB*HH), 256, ATTN_SMEM>>>(p_q, p_k, p_v, p_y);

    // stage 5: output projection (M=4096, N=1024, K=1024), tf32 mma
    mma_gemm<128,128,32,64,32><<<g2, 256>>>(p_y, wo, out, MM, EE, EE);
}

// round 8
// speedup vs baseline: 3.2249x; 1.4804x over previous
#include <cuda_runtime.h>
#include <cuda_bf16.h>
#include <cstdint>

// Problem constants
#define BB 2
#define SS 2048
#define EE 1024
#define RR 256
#define HH 16
#define MM (BB*SS)     // 4096

// ---------------- scratch (device globals; no allocation allowed) ----------
__device__ float g_xr  [MM*EE];          // tf32-rounded x
__device__ float g_w768[768*EE];         // packed [wq_down; wk_rope; wkv_down]
__device__ float g_wqp [2048*RR];        // packed [wq_rope; wq_up]
__device__ float g_wkvp[2048*RR];        // packed [wk_up; wv_up]
__device__ float g_wor [EE*EE];          // rounded wo
__device__ float g_lat3[MM*768];         // [qlat | klat | kv]
__device__ float g_qc  [MM*2048];        // [qr | qn]
__device__ float g_kc  [MM*2048];        // [kn | vf]
__device__ float g_kr  [MM*EE];
__device__ float g_q   [BB*HH*SS*128];
__device__ float g_k   [BB*HH*SS*128];
__device__ float g_v   [BB*HH*SS*64];
__device__ float g_y   [MM*EE];

// ---------------- tf32 + cp.async helpers ----------------------------------
__device__ __forceinline__ uint32_t tf32u(float x) {
    uint32_t r; asm("cvt.rna.tf32.f32 %0, %1;" : "=r"(r) : "f"(x)); return r;
}
__device__ __forceinline__ float tf32f(float x) {
    return __uint_as_float(tf32u(x));
}
__device__ __forceinline__ void mma_tf32(float4& c, const uint32_t* a, const uint32_t* b) {
    asm volatile("mma.sync.aligned.m16n8k8.row.col.f32.tf32.tf32.f32 "
        "{%0,%1,%2,%3}, {%4,%5,%6,%7}, {%8,%9}, {%0,%1,%2,%3};\n"
        : "+f"(c.x), "+f"(c.y), "+f"(c.z), "+f"(c.w)
        : "r"(a[0]), "r"(a[1]), "r"(a[2]), "r"(a[3]), "r"(b[0]), "r"(b[1]));
}
__device__ __forceinline__ void cp16(void* smem_dst, const void* gptr) {
    uint32_t sa = (uint32_t)__cvta_generic_to_shared(smem_dst);
    asm volatile("cp.async.cg.shared.global [%0], [%1], 16;\n" :: "r"(sa), "l"(gptr));
}
#define CP_COMMIT() asm volatile("cp.async.commit_group;\n" ::: "memory")
#define CP_WAIT(n)  asm volatile("cp.async.wait_group %0;\n" :: "n"(n) : "memory")

// ---------------- tf32 -> tf32-rounded copy --------------------------------
__global__ void cvt_tf32_kernel(const float* __restrict__ src,
                                float* __restrict__ dst, int n4)
{
    int i = blockIdx.x * blockDim.x + threadIdx.x;
    if (i >= n4) return;
    float4 v = ((const float4*)src)[i];
    v.x = tf32f(v.x); v.y = tf32f(v.y); v.z = tf32f(v.z); v.w = tf32f(v.w);
    ((float4*)dst)[i] = v;
}

// ---------------- tf32 tensor-core GEMM (cp.async double-buffered) ---------
// C[M,N] = A[M,K] * W[N,K]^T ; A,W pre-rounded tf32 bits. 256 thr, warp 2x4.
#define GBM 128
#define GBN 128
#define GBK 32
#define GBKP 36
#define GEMM_SMEM (2*(GBM*GBKP + GBN*GBKP)*4)

template<bool ROUND>
__global__ void __launch_bounds__(256) mma_gemm(
    const float* __restrict__ A, int lda,
    const float* __restrict__ W,
    float* __restrict__ C, int ldc, int N, int K)
{
    extern __shared__ uint32_t gsm[];
    uint32_t* As = gsm;                       // [2][GBM][GBKP]
    uint32_t* Ws = gsm + 2*GBM*GBKP;          // [2][GBN][GBKP]

    const int tid  = threadIdx.x;
    const int wid  = tid >> 5, lane = tid & 31;
    const int g    = lane >> 2, t4 = lane & 3;
    const int wr   = wid >> 2, wc = wid & 3;   // 2 x 4 warp grid (WM=64, WN=32)
    const int m0w  = wr * 64, n0w = wc * 32;
    const int m0   = blockIdx.y * GBM;
    const int n0   = blockIdx.x * GBN;

    float4 acc[4][4];
    #pragma unroll
    for (int m = 0; m < 4; m++)
        #pragma unroll
        for (int n = 0; n < 4; n++) acc[m][n] = make_float4(0.f,0.f,0.f,0.f);

    const int ntiles = K / GBK;
    // prologue: tile 0 -> buf 0
    {
        uint32_t* Ad = As; uint32_t* Wd = Ws;
        #pragma unroll
        for (int idx = tid; idx < GBM*8; idx += 256) {
            int row = idx >> 3, seg = idx & 7;
            cp16(Ad + row*GBKP + seg*4, A + (size_t)(m0+row)*lda + seg*4);
        }
        #pragma unroll
        for (int idx = tid; idx < GBN*8; idx += 256) {
            int row = idx >> 3, seg = idx & 7;
            cp16(Wd + row*GBKP + seg*4, W + (size_t)(n0+row)*K + seg*4);
        }
        CP_COMMIT();
    }

    for (int t = 0; t < ntiles; t++) {
        __syncthreads();                       // buffer (t+1)&1 fully consumed
        if (t + 1 < ntiles) {
            int kt = (t+1)*GBK;
            uint32_t* Ad = As + ((t+1)&1)*GBM*GBKP;
            uint32_t* Wd = Ws + ((t+1)&1)*GBN*GBKP;
            #pragma unroll
            for (int idx = tid; idx < GBM*8; idx += 256) {
                int row = idx >> 3, seg = idx & 7;
                cp16(Ad + row*GBKP + seg*4, A + (size_t)(m0+row)*lda + kt + seg*4);
            }
            #pragma unroll
            for (int idx = tid; idx < GBN*8; idx += 256) {
                int row = idx >> 3, seg = idx & 7;
                cp16(Wd + row*GBKP + seg*4, W + (size_t)(n0+row)*K + kt + seg*4);
            }
            CP_COMMIT();
            CP_WAIT(1);
        } else {
            CP_WAIT(0);
        }
        __syncthreads();                       // tile t visible

        const uint32_t* Ab = As + (t&1)*GBM*GBKP;
        const uint32_t* Wb = Ws + (t&1)*GBN*GBKP;
        #pragma unroll
        for (int k8 = 0; k8 < GBK; k8 += 8) {
            uint32_t bf[4][2];
            #pragma unroll
            for (int n = 0; n < 4; n++) {
                const uint32_t* bp = Wb + (n0w + n*8 + g)*GBKP + k8 + t4;
                bf[n][0] = bp[0];
                bf[n][1] = bp[4];
            }
            #pragma unroll
            for (int m = 0; m < 4; m++) {
                const uint32_t* ap = Ab + (m0w + m*16 + g)*GBKP + k8 + t4;
                uint32_t af[4] = { ap[0], ap[8*GBKP], ap[4], ap[8*GBKP + 4] };
                #pragma unroll
                for (int n = 0; n < 4; n++)
                    mma_tf32(acc[m][n], af, bf[n]);
            }
        }
    }

    #pragma unroll
    for (int m = 0; m < 4; m++) {
        #pragma unroll
        for (int n = 0; n < 4; n++) {
            int row = m0 + m0w + m*16 + g;
            int col = n0 + n0w + n*8 + 2*t4;
            float4 v = acc[m][n];
            if (ROUND) { v.x = tf32f(v.x); v.y = tf32f(v.y); v.z = tf32f(v.z); v.w = tf32f(v.w); }
            *(float2*)(C + (size_t)row*ldc + col)     = make_float2(v.x, v.y);
            *(float2*)(C + (size_t)(row+8)*ldc + col) = make_float2(v.z, v.w);
        }
    }
}

// --------- build q/k: rope(heads(rope_in)) || heads(up_in) -> [B,H,S,128] --
__global__ void build_qk_kernel(const float* __restrict__ ropein, int ldr,
                                const float* __restrict__ upin, int ldu,
                                float* __restrict__ outp, float scale)
{
    int idx = blockIdx.x * blockDim.x + threadIdx.x;   // over B*H*S*64
    if (idx >= BB*HH*SS*64) return;
    int d = idx & 63;
    int s = (idx >> 6) & (SS-1);
    int h = (idx >> 17) & (HH-1);
    int b = idx >> 21;
    const size_t rbase = (size_t)(b*SS + s)*ldr + h*64;
    const size_t ubase = (size_t)(b*SS + s)*ldu + h*64;
    float x1 = ropein[rbase + d];
    float rot; int fi;
    if (d < 32) { rot = -ropein[rbase + d + 32]; fi = d; }
    else        { rot =  ropein[rbase + d - 32]; fi = d - 32; }
    float inv = __powf(10000.0f, -(float)(2*fi) * (1.0f/64.0f));
    float ang = (float)s * inv;
    float sn, cs; sincosf(ang, &sn, &cs);
    float val = fmaf(x1, cs, rot*sn);
    const int ob = ((b*HH + h)*SS + s)*128;
    outp[ob + d]      = tf32f(val * scale);
    outp[ob + 64 + d] = tf32f(upin[ubase + d] * scale);
}

__global__ void build_v_kernel(const float* __restrict__ vf, int ldv,
                               float* __restrict__ vout)
{
    int idx = blockIdx.x * blockDim.x + threadIdx.x;   // over B*H*S*64
    if (idx >= BB*HH*SS*64) return;
    int d = idx & 63;
    int s = (idx >> 6) & (SS-1);
    int h = (idx >> 17) & (HH-1);
    int b = idx >> 21;
    vout[idx] = tf32f(vf[(size_t)(b*SS + s)*ldv + h*64 + d]);
}

// ---------------- causal flash attention, tf32 mma, cp.async ----------------
// Q,K: [B,H,S,128] tf32 bits (Q pre-scaled), V: [B,H,S,64] tf32 bits
// CTA: 128 q-rows x one (b,h); 256 thr = 8 warps (4 row x 2 col), K-tile 64.
#define ATQ 128
#define ATK 64
#define QSTR 136
#define VSTR 72
#define PSTR 72
#define ATTN_SMEM ((ATQ*QSTR + 2*ATK*QSTR + 2*ATK*VSTR + ATQ*PSTR + 2*128 + 2*128 + 128 + 128) * 4)

__global__ void __launch_bounds__(256) attn_mma(
    const float* __restrict__ Q, const float* __restrict__ Kg,
    const float* __restrict__ Vg, float* __restrict__ Y)
{
    extern __shared__ __align__(16) uint32_t smu[];
    uint32_t* Qs   = smu;                          // [128][QSTR]
    uint32_t* Ks   = Qs + ATQ*QSTR;                // [2][64][QSTR]
    uint32_t* Vs   = Ks + 2*ATK*QSTR;              // [2][64][VSTR]
    uint32_t* Ps   = Vs + 2*ATK*VSTR;              // [128][PSTR]
    float* redmax  = (float*)(Ps + ATQ*PSTR);      // [2][128]
    float* redsum  = redmax + 2*128;               // [2][128]
    float* msm     = redsum + 2*128;               // [128]
    float* lsm     = msm + 128;                    // [128]

    const int tid = threadIdx.x;
    const int lane = tid & 31, wid = tid >> 5;
    const int g = lane >> 2, t4 = lane & 3;
    const int wrs = wid >> 1, wcs = wid & 1;
    const int q0 = ((int)gridDim.x - 1 - (int)blockIdx.x) * ATQ;  // heavy first
    const int bh = blockIdx.y, b = bh >> 4, h = bh & 15;

    const float* qbase = Q + ((size_t)bh*SS + q0)*128;
    const float* kbase = Kg + (size_t)bh*SS*128;
    const float* vbase = Vg + (size_t)bh*SS*64;

    if (tid < 128) { msm[tid] = -1e30f; lsm[tid] = 0.f; }

    // prologue: Q + K/V tile 0 via cp.async (group 0)
    #pragma unroll
    for (int idx = tid; idx < ATQ*32; idx += 256) {
        int row = idx >> 5, seg = idx & 31;
        cp16(Qs + row*QSTR + seg*4, qbase + row*128 + seg*4);
    }
    #pragma unroll
    for (int idx = tid; idx < ATK*32; idx += 256) {
        int row = idx >> 5, seg = idx & 31;
        cp16(Ks + row*QSTR + seg*4, kbase + (size_t)row*128 + seg*4);
    }
    #pragma unroll
    for (int idx = tid; idx < ATK*16; idx += 256) {
        int row = idx >> 4, seg = idx & 15;
        cp16(Vs + row*VSTR + seg*4, vbase + (size_t)row*64 + seg*4);
    }
    CP_COMMIT();

    float4 oacc[2][4];
    #pragma unroll
    for (int m = 0; m < 2; m++)
        #pragma unroll
        for (int n = 0; n < 4; n++) oacc[m][n] = make_float4(0.f,0.f,0.f,0.f);

    const int ntiles = q0/ATK + 2;

    for (int t = 0; t < ntiles; t++) {
        __syncthreads();                 // buffer (t+1)&1 fully consumed
        if (t + 1 < ntiles) {
            int k0n = (t+1)*ATK;
            uint32_t* Kd = Ks + ((t+1)&1)*ATK*QSTR;
            uint32_t* Vd = Vs + ((t+1)&1)*ATK*VSTR;
            #pragma unroll
            for (int idx = tid; idx < ATK*32; idx += 256) {
                int row = idx >> 5, seg = idx & 31;
                cp16(Kd + row*QSTR + seg*4, kbase + (size_t)(k0n+row)*128 + seg*4);
            }
            #pragma unroll
            for (int idx = tid; idx < ATK*16; idx += 256) {
                int row = idx >> 4, seg = idx & 15;
                cp16(Vd + row*VSTR + seg*4, vbase + (size_t)(k0n+row)*64 + seg*4);
            }
            CP_COMMIT();
            CP_WAIT(1);
        } else {
            CP_WAIT(0);
        }
        __syncthreads();                 // tile t visible

        const int k0 = t*ATK;
        const uint32_t* Kb = Ks + (t&1)*ATK*QSTR;
        const uint32_t* Vb = Vs + (t&1)*ATK*VSTR;

        // ---- S = Q @ K^T (128x64), warp tile 32x32 ----
        float4 sf[2][4];
        #pragma unroll
        for (int m = 0; m < 2; m++)
            #pragma unroll
            for (int n = 0; n < 4; n++) sf[m][n] = make_float4(0.f,0.f,0.f,0.f);

        #pragma unroll
        for (int d8 = 0; d8 < 128; d8 += 8) {
            uint32_t bf[4][2];
            #pragma unroll
            for (int n = 0; n < 4; n++) {
                const uint32_t* bp = Kb + (wcs*32 + n*8 + g)*QSTR + d8 + t4;
                bf[n][0] = bp[0];
                bf[n][1] = bp[4];
            }
            #pragma unroll
            for (int m = 0; m < 2; m++) {
                const uint32_t* ap = Qs + (wrs*32 + m*16 + g)*QSTR + d8 + t4;
                uint32_t af[4] = { ap[0], ap[8*QSTR], ap[4], ap[8*QSTR + 4] };
                #pragma unroll
                for (int n = 0; n < 4; n++) mma_tf32(sf[m][n], af, bf[n]);
            }
        }

        // ---- causal mask in registers ----
        if (k0 + ATK - 1 > q0) {
            #pragma unroll
            for (int m = 0; m < 2; m++) {
                int lr = wrs*32 + m*16 + g;
                #pragma unroll
                for (int n = 0; n < 4; n++) {
                    int lc = wcs*32 + n*8 + 2*t4;
                    int qr = q0 + lr, kc = k0 + lc;
                    if (kc     > qr)     sf[m][n].x = -1e30f;
                    if (kc + 1 > qr)     sf[m][n].y = -1e30f;
                    if (kc     > qr + 8) sf[m][n].z = -1e30f;
                    if (kc + 1 > qr + 8) sf[m][n].w = -1e30f;
                }
            }
        }

        // ---- register softmax: rows R0+8j owned by this thread ----
        const int R0 = wrs*32 + g;
        float rmax[4];
        rmax[0] = fmaxf(fmaxf(sf[0][0].x, sf[0][0].y), fmaxf(sf[0][1].x, sf[0][1].y));
        rmax[0] = fmaxf(rmax[0], fmaxf(fmaxf(sf[0][2].x, sf[0][2].y), fmaxf(sf[0][3].x, sf[0][3].y)));
        rmax[1] = fmaxf(fmaxf(sf[0][0].z, sf[0][0].w), fmaxf(sf[0][1].z, sf[0][1].w));
        rmax[1] = fmaxf(rmax[1], fmaxf(fmaxf(sf[0][2].z, sf[0][2].w), fmaxf(sf[0][3].z, sf[0][3].w)));
        rmax[2] = fmaxf(fmaxf(sf[1][0].x, sf[1][0].y), fmaxf(sf[1][1].x, sf[1][1].y));
        rmax[2] = fmaxf(rmax[2], fmaxf(fmaxf(sf[1][2].x, sf[1][2].y), fmaxf(sf[1][3].x, sf[1][3].y)));
        rmax[3] = fmaxf(fmaxf(sf[1][0].z, sf[1][0].w), fmaxf(sf[1][1].z, sf[1][1].w));
        rmax[3] = fmaxf(rmax[3], fmaxf(fmaxf(sf[1][2].z, sf[1][2].w), fmaxf(sf[1][3].z, sf[1][3].w)));
        #pragma unroll
        for (int j = 0; j < 4; j++) {
            rmax[j] = fmaxf(rmax[j], __shfl_xor_sync(0xffffffffu, rmax[j], 1));
            rmax[j] = fmaxf(rmax[j], __shfl_xor_sync(0xffffffffu, rmax[j], 2));
        }
        if (t4 == 0) {
            #pragma unroll
            for (int j = 0; j < 4; j++) redmax[wcs*128 + R0 + j*8] = rmax[j];
        }
        __syncthreads();                 // C: row maxima combined

        float mnew[4], al[4];
        #pragma unroll
        for (int j = 0; j < 4; j++) {
            int r = R0 + j*8;
            float mo = msm[r];
            mnew[j] = fmaxf(mo, fmaxf(redmax[r], redmax[128 + r]));
            al[j] = __expf(mo - mnew[j]);
        }
        float rsum[4] = {0.f, 0.f, 0.f, 0.f};
        #pragma unroll
        for (int m = 0; m < 2; m++) {
            #pragma unroll
            for (int n = 0; n < 4; n++) {
                sf[m][n].x = __expf(sf[m][n].x - mnew[2*m]);   rsum[2*m]   += sf[m][n].x;
                sf[m][n].y = __expf(sf[m][n].y - mnew[2*m]);   rsum[2*m]   += sf[m][n].y;
                sf[m][n].z = __expf(sf[m][n].z - mnew[2*m+1]); rsum[2*m+1] += sf[m][n].z;
                sf[m][n].w = __expf(sf[m][n].w - mnew[2*m+1]); rsum[2*m+1] += sf[m][n].w;
            }
        }
        #pragma unroll
        for (int j = 0; j < 4; j++) {
            rsum[j] += __shfl_xor_sync(0xffffffffu, rsum[j], 1);
            rsum[j] += __shfl_xor_sync(0xffffffffu, rsum[j], 2);
        }
        if (t4 == 0) {
            #pragma unroll
            for (int j = 0; j < 4; j++) redsum[wcs*128 + R0 + j*8] = rsum[j];
        }

        // rescale O and write P (tf32) to smem
        #pragma unroll
        for (int m = 0; m < 2; m++) {
            #pragma unroll
            for (int n = 0; n < 4; n++) {
                oacc[m][n].x *= al[2*m];   oacc[m][n].y *= al[2*m];
                oacc[m][n].z *= al[2*m+1]; oacc[m][n].w *= al[2*m+1];
                int col = wcs*32 + n*8 + 2*t4;
                int row = wrs*32 + m*16 + g;
                *(uint2*)(Ps + row*PSTR + col)     = make_uint2(tf32u(sf[m][n].x), tf32u(sf[m][n].y));
                *(uint2*)(Ps + (row+8)*PSTR + col) = make_uint2(tf32u(sf[m][n].z), tf32u(sf[m][n].w));
            }
        }
        __syncthreads();                 // D: P + row sums complete

        if (tid < 128) {
            int r = tid;
            float mo = msm[r];
            float mn = fmaxf(mo, fmaxf(redmax[r], redmax[128 + r]));
            lsm[r] = lsm[r]*__expf(mo - mn) + redsum[r] + redsum[128 + r];
            msm[r] = mn;
        }

        // ---- O += P @ V ----
        #pragma unroll
        for (int k8 = 0; k8 < ATK; k8 += 8) {
            uint32_t bf[4][2];
            #pragma unroll
            for (int n = 0; n < 4; n++) {
                const uint32_t* bp = Vb + (k8 + t4)*VSTR + wcs*32 + n*8 + g;
                bf[n][0] = bp[0];
                bf[n][1] = bp[4*VSTR];
            }
            #pragma unroll
            for (int m = 0; m < 2; m++) {
                const uint32_t* ap = Ps + (wrs*32 + m*16 + g)*PSTR + k8 + t4;
                uint32_t af[4] = { ap[0], ap[8*PSTR], ap[4], ap[8*PSTR + 4] };
                #pragma unroll
                for (int n = 0; n < 4; n++) mma_tf32(oacc[m][n], af, bf[n]);
            }
        }
    }

    __syncthreads();                     // lsm final
    #pragma unroll
    for (int m = 0; m < 2; m++) {
        int lr = wrs*32 + m*16 + g;
        float i0 = 1.f / lsm[lr], i1 = 1.f / lsm[lr+8];
        #pragma unroll
        for (int n = 0; n < 4; n++) {
            int lc = wcs*32 + n*8 + 2*t4;
            float* yp  = Y + ((size_t)b*SS + q0 + lr)*EE + h*64 + lc;
            *(float2*)yp  = make_float2(tf32f(oacc[m][n].x*i0), tf32f(oacc[m][n].y*i0));
            float* yp2 = Y + ((size_t)b*SS + q0 + lr + 8)*EE + h*64 + lc;
            *(float2*)yp2 = make_float2(tf32f(oacc[m][n].z*i1), tf32f(oacc[m][n].w*i1));
        }
    }
}

// ---------------- host launcher --------------------------------------------
extern "C" void kernel_launch(void* const* d_in, const int* in_sizes, int n_in,
                              void* d_out, int out_size)
{
    const float* x       = (const float*)d_in[0];
    const float* wq_down = (const float*)d_in[1];
    const float* wk_rope = (const float*)d_in[2];
    const float* wkv_down= (const float*)d_in[3];
    const float* wq_rope = (const float*)d_in[4];
    const float* wq_up   = (const float*)d_in[5];
    const float* wk_up   = (const float*)d_in[6];
    const float* wv_up   = (const float*)d_in[7];
    const float* wo      = (const float*)d_in[8];
    float* out = (float*)d_out;

    static float *p_xr=nullptr,*p_w768=nullptr,*p_wqp=nullptr,*p_wkvp=nullptr,*p_wor=nullptr,
                 *p_lat3=nullptr,*p_qc=nullptr,*p_kc=nullptr,*p_kr=nullptr,
                 *p_q=nullptr,*p_k=nullptr,*p_v=nullptr,*p_y=nullptr;
    static bool inited = false;
    if (!inited) {
        cudaGetSymbolAddress((void**)&p_xr,   g_xr);
        cudaGetSymbolAddress((void**)&p_w768, g_w768);
        cudaGetSymbolAddress((void**)&p_wqp,  g_wqp);
        cudaGetSymbolAddress((void**)&p_wkvp, g_wkvp);
        cudaGetSymbolAddress((void**)&p_wor,  g_wor);
        cudaGetSymbolAddress((void**)&p_lat3, g_lat3);
        cudaGetSymbolAddress((void**)&p_qc,   g_qc);
        cudaGetSymbolAddress((void**)&p_kc,   g_kc);
        cudaGetSymbolAddress((void**)&p_kr,   g_kr);
        cudaGetSymbolAddress((void**)&p_q,    g_q);
        cudaGetSymbolAddress((void**)&p_k,    g_k);
        cudaGetSymbolAddress((void**)&p_v,    g_v);
        cudaGetSymbolAddress((void**)&p_y,    g_y);
        cudaFuncSetAttribute(attn_mma,
            cudaFuncAttributeMaxDynamicSharedMemorySize, (int)ATTN_SMEM);
        cudaFuncSetAttribute(mma_gemm<true>,
            cudaFuncAttributeMaxDynamicSharedMemorySize, (int)GEMM_SMEM);
        cudaFuncSetAttribute(mma_gemm<false>,
            cudaFuncAttributeMaxDynamicSharedMemorySize, (int)GEMM_SMEM);
        inited = true;
    }

    // stage 0: tf32 pre-rounding / packing
    {
        int n4;
        n4 = MM*EE/4;  cvt_tf32_kernel<<<(n4+255)/256, 256>>>(x, p_xr, n4);
        n4 = RR*EE/4;
        cvt_tf32_kernel<<<(n4+255)/256, 256>>>(wq_down,  p_w768,             n4);
        cvt_tf32_kernel<<<(n4+255)/256, 256>>>(wk_rope,  p_w768 + RR*EE,     n4);
        cvt_tf32_kernel<<<(n4+255)/256, 256>>>(wkv_down, p_w768 + 2*RR*EE,   n4);
        n4 = EE*RR/4;
        cvt_tf32_kernel<<<(n4+255)/256, 256>>>(wq_rope,  p_wqp,              n4);
        cvt_tf32_kernel<<<(n4+255)/256, 256>>>(wq_up,    p_wqp + EE*RR,      n4);
        cvt_tf32_kernel<<<(n4+255)/256, 256>>>(wk_up,    p_wkvp,             n4);
        cvt_tf32_kernel<<<(n4+255)/256, 256>>>(wv_up,    p_wkvp + EE*RR,     n4);
        n4 = EE*EE/4;  cvt_tf32_kernel<<<(n4+255)/256, 256>>>(wo, p_wor, n4);
    }

    // stage 1: fused down projections: lat3 = x @ [wq_down;wk_rope;wkv_down]^T
    mma_gemm<true><<<dim3(768/GBN, MM/GBM), 256, GEMM_SMEM>>>(
        p_xr, EE, p_w768, p_lat3, 768, 768, EE);

    // stage 2: up projections
    mma_gemm<false><<<dim3(2048/GBN, MM/GBM), 256, GEMM_SMEM>>>(
        p_lat3 + 0,   768, p_wqp,  p_qc, 2048, 2048, RR);   // qlat -> [qr|qn]
    mma_gemm<false><<<dim3(2048/GBN, MM/GBM), 256, GEMM_SMEM>>>(
        p_lat3 + 512, 768, p_wkvp, p_kc, 2048, 2048, RR);   // kv   -> [kn|vf]
    mma_gemm<false><<<dim3(1024/GBN, MM/GBM), 256, GEMM_SMEM>>>(
        p_lat3 + 256, 768, p_wkvp, p_kr, 1024, 1024, RR);   // klat -> kr

    // stage 3: head layout + RoPE (tf32-rounded; q pre-scaled by 1/sqrt(128))
    int nb = (BB*HH*SS*64 + 255) / 256;
    build_qk_kernel<<<nb, 256>>>(p_qc, 2048, p_qc + 1024, 2048, p_q, 0.08838834764831845f);
    build_qk_kernel<<<nb, 256>>>(p_kr, 1024, p_kc,        2048, p_k, 1.0f);
    build_v_kernel<<<nb, 256>>>(p_kc + 1024, 2048, p_v);

    // stage 4: causal flash attention on tensor cores
    attn_mma<<<dim3(SS/ATQ, BB*HH), 256, ATTN_SMEM>>>(p_q, p_k, p_v, p_y);

    // stage 5: output projection
    mma_gemm<false><<<dim3(EE/GBN, MM/GBM), 256, GEMM_SMEM>>>(
        p_y, EE, p_wor, out, EE, EE, EE);
}

// round 13
// speedup vs baseline: 3.7700x; 1.1690x over previous
#include <cuda_runtime.h>
#include <cuda_bf16.h>
#include <cstdint>

// Problem constants
#define BB 2
#define SS 2048
#define EE 1024
#define RR 256
#define HH 16
#define MM (BB*SS)     // 4096

// ---------------- scratch (device globals; no allocation allowed) ----------
__device__ float g_xr  [MM*EE];          // tf32-rounded x
__device__ float g_w768[768*EE];         // packed [wq_down; wk_rope; wkv_down]
__device__ float g_wqp [2048*RR];        // packed [wq_rope; wq_up]
__device__ float g_wkvp[2048*RR];        // packed [wk_up; wv_up]
__device__ float g_wor [EE*EE];          // rounded wo
__device__ float g_lat3[MM*768];         // [qlat | klat | kv]
__device__ float g_qc  [MM*2048];        // [qr | qn]
__device__ float g_kc  [MM*2048];        // [kn | vf]
__device__ float g_kr  [MM*EE];
__device__ float g_q   [BB*HH*SS*128];   // d-permuted within 8-groups
__device__ float g_k   [BB*HH*SS*128];   // d-permuted within 8-groups
__device__ float g_vt  [BB*HH*64*SS];    // [bh][d][s], s permuted within 8-groups
__device__ float g_y   [MM*EE];

// ---------------- tf32 + cp.async helpers ----------------------------------
__device__ __forceinline__ uint32_t tf32u(float x) {
    uint32_t r; asm("cvt.rna.tf32.f32 %0, %1;" : "=r"(r) : "f"(x)); return r;
}
__device__ __forceinline__ float tf32f(float x) {
    return __uint_as_float(tf32u(x));
}
__device__ __forceinline__ void mma_tf32(float4& c, const uint32_t* a, const uint32_t* b) {
    asm volatile("mma.sync.aligned.m16n8k8.row.col.f32.tf32.tf32.f32 "
        "{%0,%1,%2,%3}, {%4,%5,%6,%7}, {%8,%9}, {%0,%1,%2,%3};\n"
        : "+f"(c.x), "+f"(c.y), "+f"(c.z), "+f"(c.w)
        : "r"(a[0]), "r"(a[1]), "r"(a[2]), "r"(a[3]), "r"(b[0]), "r"(b[1]));
}
__device__ __forceinline__ void cp16(void* smem_dst, const void* gptr) {
    uint32_t sa = (uint32_t)__cvta_generic_to_shared(smem_dst);
    asm volatile("cp.async.cg.shared.global [%0], [%1], 16;\n" :: "r"(sa), "l"(gptr));
}
#define CP_COMMIT() asm volatile("cp.async.commit_group;\n" ::: "memory")
#define CP_WAIT(n)  asm volatile("cp.async.wait_group %0;\n" :: "n"(n) : "memory")

// ---------------- fused tf32 rounding of all inputs ------------------------
// float4 ranges: x 1048576 | 3x65536 (w768) | 4x65536 (wqp,wkvp) | wo 262144
__global__ void cvt_all_kernel(
    const float* __restrict__ x,
    const float* __restrict__ w1, const float* __restrict__ w2, const float* __restrict__ w3,
    const float* __restrict__ w4, const float* __restrict__ w5, const float* __restrict__ w6,
    const float* __restrict__ w7, const float* __restrict__ wo,
    float* __restrict__ xr, float* __restrict__ w768,
    float* __restrict__ wqp, float* __restrict__ wkvp, float* __restrict__ wor)
{
    int i = blockIdx.x * blockDim.x + threadIdx.x;
    const float4* s; float4* d; int off;
    if (i < 1048576)      { s = (const float4*)x;  d = (float4*)xr;   off = i; }
    else if (i < 1114112) { s = (const float4*)w1; d = (float4*)w768; off = i - 1048576;
                            d += 0; }
    else if (i < 1179648) { s = (const float4*)w2; d = (float4*)(w768 + RR*EE); off = i - 1114112; }
    else if (i < 1245184) { s = (const float4*)w3; d = (float4*)(w768 + 2*RR*EE); off = i - 1179648; }
    else if (i < 1310720) { s = (const float4*)w4; d = (float4*)wqp; off = i - 1245184; }
    else if (i < 1376256) { s = (const float4*)w5; d = (float4*)(wqp + EE*RR); off = i - 1310720; }
    else if (i < 1441792) { s = (const float4*)w6; d = (float4*)wkvp; off = i - 1376256; }
    else if (i < 1507328) { s = (const float4*)w7; d = (float4*)(wkvp + EE*RR); off = i - 1441792; }
    else if (i < 1769472) { s = (const float4*)wo; d = (float4*)wor; off = i - 1507328; }
    else return;
    float4 v = s[off];
    v.x = tf32f(v.x); v.y = tf32f(v.y); v.z = tf32f(v.z); v.w = tf32f(v.w);
    d[off] = v;
}

// ---------------- tf32 tensor-core GEMM (cp.async double-buffered) ---------
// C[M,N] = A[M,K] * W[N,K]^T ; A,W pre-rounded tf32 bits. 256 thr, warp 2x4.
#define GBM 128
#define GBN 128
#define GBK 32
#define GBKP 36
#define GEMM_SMEM (2*(GBM*GBKP + GBN*GBKP)*4)

template<bool ROUND>
__global__ void __launch_bounds__(256, 2) mma_gemm(
    const float* __restrict__ A, int lda,
    const float* __restrict__ W,
    float* __restrict__ C, int ldc, int N, int K)
{
    extern __shared__ uint32_t gsm[];
    uint32_t* As = gsm;                       // [2][GBM][GBKP]
    uint32_t* Ws = gsm + 2*GBM*GBKP;          // [2][GBN][GBKP]

    const int tid  = threadIdx.x;
    const int wid  = tid >> 5, lane = tid & 31;
    const int g    = lane >> 2, t4 = lane & 3;
    const int wr   = wid >> 2, wc = wid & 3;   // 2 x 4 warp grid (WM=64, WN=32)
    const int m0w  = wr * 64, n0w = wc * 32;
    const int m0   = blockIdx.y * GBM;
    const int n0   = blockIdx.x * GBN;

    float4 acc[4][4];
    #pragma unroll
    for (int m = 0; m < 4; m++)
        #pragma unroll
        for (int n = 0; n < 4; n++) acc[m][n] = make_float4(0.f,0.f,0.f,0.f);

    const int ntiles = K / GBK;
    {
        #pragma unroll
        for (int idx = tid; idx < GBM*8; idx += 256) {
            int row = idx >> 3, seg = idx & 7;
            cp16(As + row*GBKP + seg*4, A + (size_t)(m0+row)*lda + seg*4);
        }
        #pragma unroll
        for (int idx = tid; idx < GBN*8; idx += 256) {
            int row = idx >> 3, seg = idx & 7;
            cp16(Ws + row*GBKP + seg*4, W + (size_t)(n0+row)*K + seg*4);
        }
        CP_COMMIT();
    }

    for (int t = 0; t < ntiles; t++) {
        __syncthreads();
        if (t + 1 < ntiles) {
            int kt = (t+1)*GBK;
            uint32_t* Ad = As + ((t+1)&1)*GBM*GBKP;
            uint32_t* Wd = Ws + ((t+1)&1)*GBN*GBKP;
            #pragma unroll
            for (int idx = tid; idx < GBM*8; idx += 256) {
                int row = idx >> 3, seg = idx & 7;
                cp16(Ad + row*GBKP + seg*4, A + (size_t)(m0+row)*lda + kt + seg*4);
            }
            #pragma unroll
            for (int idx = tid; idx < GBN*8; idx += 256) {
                int row = idx >> 3, seg = idx & 7;
                cp16(Wd + row*GBKP + seg*4, W + (size_t)(n0+row)*K + kt + seg*4);
            }
            CP_COMMIT();
            CP_WAIT(1);
        } else {
            CP_WAIT(0);
        }
        __syncthreads();

        const uint32_t* Ab = As + (t&1)*GBM*GBKP;
        const uint32_t* Wb = Ws + (t&1)*GBN*GBKP;
        #pragma unroll
        for (int k8 = 0; k8 < GBK; k8 += 8) {
            uint32_t bf[4][2];
            #pragma unroll
            for (int n = 0; n < 4; n++) {
                const uint32_t* bp = Wb + (n0w + n*8 + g)*GBKP + k8 + t4;
                bf[n][0] = bp[0];
                bf[n][1] = bp[4];
            }
            #pragma unroll
            for (int m = 0; m < 4; m++) {
                const uint32_t* ap = Ab + (m0w + m*16 + g)*GBKP + k8 + t4;
                uint32_t af[4] = { ap[0], ap[8*GBKP], ap[4], ap[8*GBKP + 4] };
                #pragma unroll
                for (int n = 0; n < 4; n++)
                    mma_tf32(acc[m][n], af, bf[n]);
            }
        }
    }

    #pragma unroll
    for (int m = 0; m < 4; m++) {
        #pragma unroll
        for (int n = 0; n < 4; n++) {
            int row = m0 + m0w + m*16 + g;
            int col = n0 + n0w + n*8 + 2*t4;
            float4 v = acc[m][n];
            if (ROUND) { v.x = tf32f(v.x); v.y = tf32f(v.y); v.z = tf32f(v.z); v.w = tf32f(v.w); }
            *(float2*)(C + (size_t)row*ldc + col)     = make_float2(v.x, v.y);
            *(float2*)(C + (size_t)(row+8)*ldc + col) = make_float2(v.z, v.w);
        }
    }
}

// --------- build q/k: rope||up -> [B,H,S,128], d permuted within 8-groups --
__global__ void build_qk_kernel(const float* __restrict__ ropein, int ldr,
                                const float* __restrict__ upin, int ldu,
                                float* __restrict__ outp, float scale)
{
    int idx = blockIdx.x * blockDim.x + threadIdx.x;   // over B*H*S*64
    if (idx >= BB*HH*SS*64) return;
    int d = idx & 63;
    int s = (idx >> 6) & (SS-1);
    int h = (idx >> 17) & (HH-1);
    int b = idx >> 21;
    const size_t rbase = (size_t)(b*SS + s)*ldr + h*64;
    const size_t ubase = (size_t)(b*SS + s)*ldu + h*64;
    float x1 = ropein[rbase + d];
    float rot; int fi;
    if (d < 32) { rot = -ropein[rbase + d + 32]; fi = d; }
    else        { rot =  ropein[rbase + d - 32]; fi = d - 32; }
    float inv = __powf(10000.0f, -(float)(2*fi) * (1.0f/64.0f));
    float ang = (float)s * inv;
    float sn, cs; sincosf(ang, &sn, &cs);
    float val = fmaf(x1, cs, rot*sn);
    const int ob = ((b*HH + h)*SS + s)*128;
    const int dp = (d & ~7) | (2*(d & 3) + ((d >> 2) & 1));   // LDS.64 perm
    outp[ob + dp]      = tf32f(val * scale);
    outp[ob + 64 + dp] = tf32f(upin[ubase + d] * scale);
}

// --------- build Vt: [bh][d][s], s permuted within 8-groups ----------------
// tiled transpose: grid (D/32=2, S/32=64, BH=32), block (32, 8)
__global__ void build_vt_kernel(const float* __restrict__ vf, int ldv,
                                float* __restrict__ vt)
{
    __shared__ float tile[32][33];
    const int bh = blockIdx.z, h = bh & 15, b = bh >> 4;
    const int d0 = blockIdx.x * 32, s0 = blockIdx.y * 32;
    const int tx = threadIdx.x, ty = threadIdx.y;
    #pragma unroll
    for (int i = 0; i < 4; i++) {
        int sl = ty + i*8;
        tile[sl][tx] = vf[(size_t)(b*SS + s0 + sl)*ldv + h*64 + d0 + tx];
    }
    __syncthreads();
    const int sp = (tx & ~7) | (2*(tx & 3) + ((tx >> 2) & 1));
    #pragma unroll
    for (int i = 0; i < 4; i++) {
        int dl = ty + i*8;
        vt[((size_t)bh*64 + d0 + dl)*SS + s0 + sp] = tf32f(tile[tx][dl]);
    }
}

// ---------------- causal flash attention, tf32 mma, cp.async ----------------
// Q,K: [B,H,S,128] tf32 bits, d-permuted (Q pre-scaled); Vt: [bh][64][S] s-perm
// CTA: 128 q-rows x one (b,h); 8 warps, each owns 16 rows x all 64 cols.
#define ATQ 128
#define ATK 64
#define QSTR 136
#define VTSTR 72
#define PSTR 72
#define ATTN_SMEM ((ATQ*QSTR + 2*ATK*QSTR + 2*64*VTSTR + ATQ*PSTR) * 4)

__global__ void __launch_bounds__(256) attn_mma(
    const float* __restrict__ Q, const float* __restrict__ Kg,
    const float* __restrict__ Vtg, float* __restrict__ Y)
{
    extern __shared__ __align__(16) uint32_t smu[];
    uint32_t* Qs = smu;                    // [128][QSTR]
    uint32_t* Ks = Qs + ATQ*QSTR;          // [2][64][QSTR]
    uint32_t* Vt = Ks + 2*ATK*QSTR;        // [2][64][VTSTR]  rows=d, cols=keys(perm)
    uint32_t* Ps = Vt + 2*64*VTSTR;        // [128][PSTR]     warp-private slices

    const int tid = threadIdx.x;
    const int lane = tid & 31, wid = tid >> 5;
    const int g = lane >> 2, t4 = lane & 3;
    const int q0 = ((int)gridDim.x - 1 - (int)blockIdx.x) * ATQ;  // heavy first
    const int bh = blockIdx.y, b = bh >> 4, h = bh & 15;

    const float* qbase  = Q + ((size_t)bh*SS + q0)*128;
    const float* kbase  = Kg + (size_t)bh*SS*128;
    const float* vtbase = Vtg + (size_t)bh*64*SS;

    // prologue: Q + K/V tile 0
    #pragma unroll
    for (int idx = tid; idx < ATQ*32; idx += 256) {
        int row = idx >> 5, seg = idx & 31;
        cp16(Qs + row*QSTR + seg*4, qbase + row*128 + seg*4);
    }
    #pragma unroll
    for (int idx = tid; idx < ATK*32; idx += 256) {
        int row = idx >> 5, seg = idx & 31;
        cp16(Ks + row*QSTR + seg*4, kbase + (size_t)row*128 + seg*4);
    }
    #pragma unroll
    for (int idx = tid; idx < 64*16; idx += 256) {
        int row = idx >> 4, seg = idx & 15;
        cp16(Vt + row*VTSTR + seg*4, vtbase + (size_t)row*SS + seg*4);
    }
    CP_COMMIT();

    float4 sf[8], oacc[8];
    #pragma unroll
    for (int j = 0; j < 8; j++) oacc[j] = make_float4(0.f,0.f,0.f,0.f);
    float m0r = -1e30f, m1r = -1e30f, l0r = 0.f, l1r = 0.f;

    const int r0 = wid*16 + g;                 // warp's row (and r0+8)
    uint32_t* Pw = Ps + wid*16*PSTR;           // warp-private P slice

    const int ntiles = q0/ATK + 2;

    for (int t = 0; t < ntiles; t++) {
        __syncthreads();                 // buffer (t+1)&1 fully consumed
        if (t + 1 < ntiles) {
            int k0n = (t+1)*ATK;
            uint32_t* Kd = Ks + ((t+1)&1)*ATK*QSTR;
            uint32_t* Vd = Vt + ((t+1)&1)*64*VTSTR;
            #pragma unroll
            for (int idx = tid; idx < ATK*32; idx += 256) {
                int row = idx >> 5, seg = idx & 31;
                cp16(Kd + row*QSTR + seg*4, kbase + (size_t)(k0n+row)*128 + seg*4);
            }
            #pragma unroll
            for (int idx = tid; idx < 64*16; idx += 256) {
                int row = idx >> 4, seg = idx & 15;
                cp16(Vd + row*VTSTR + seg*4, vtbase + (size_t)row*SS + k0n + seg*4);
            }
            CP_COMMIT();
            CP_WAIT(1);
        } else {
            CP_WAIT(0);
        }
        __syncthreads();                 // tile t visible

        const int k0 = t*ATK;
        const uint32_t* Kb = Ks + (t&1)*ATK*QSTR;
        const uint32_t* Vb = Vt + (t&1)*64*VTSTR;

        // ---- S = Q @ K^T : warp computes 16 rows x 64 cols ----
        #pragma unroll
        for (int j = 0; j < 8; j++) sf[j] = make_float4(0.f,0.f,0.f,0.f);

        #pragma unroll
        for (int d8 = 0; d8 < 128; d8 += 8) {
            uint2 alo = *(const uint2*)(Qs + r0*QSTR + d8 + 2*t4);
            uint2 ahi = *(const uint2*)(Qs + (r0+8)*QSTR + d8 + 2*t4);
            uint32_t af[4] = { alo.x, ahi.x, alo.y, ahi.y };
            #pragma unroll
            for (int j = 0; j < 8; j++) {
                uint2 bv = *(const uint2*)(Kb + (j*8+g)*QSTR + d8 + 2*t4);
                uint32_t bfr[2] = { bv.x, bv.y };
                mma_tf32(sf[j], af, bfr);
            }
        }

        // ---- causal mask (register) ----
        if (k0 + ATK - 1 > q0 + wid*16) {
            const int qr0 = q0 + r0, qr1 = qr0 + 8;
            #pragma unroll
            for (int j = 0; j < 8; j++) {
                int c0 = k0 + j*8 + 2*t4, c1 = c0 + 1;
                if (c0 > qr0) sf[j].x = -1e30f;
                if (c1 > qr0) sf[j].y = -1e30f;
                if (c0 > qr1) sf[j].z = -1e30f;
                if (c1 > qr1) sf[j].w = -1e30f;
            }
        }

        // ---- warp-local online softmax (rows r0, r0+8) ----
        float mx0 = -1e30f, mx1 = -1e30f;
        #pragma unroll
        for (int j = 0; j < 8; j++) {
            mx0 = fmaxf(mx0, fmaxf(sf[j].x, sf[j].y));
            mx1 = fmaxf(mx1, fmaxf(sf[j].z, sf[j].w));
        }
        mx0 = fmaxf(mx0, __shfl_xor_sync(0xffffffffu, mx0, 1));
        mx0 = fmaxf(mx0, __shfl_xor_sync(0xffffffffu, mx0, 2));
        mx1 = fmaxf(mx1, __shfl_xor_sync(0xffffffffu, mx1, 1));
        mx1 = fmaxf(mx1, __shfl_xor_sync(0xffffffffu, mx1, 2));

        float mn0 = fmaxf(m0r, mx0), mn1 = fmaxf(m1r, mx1);
        float al0 = __expf(m0r - mn0), al1 = __expf(m1r - mn1);
        float s0 = 0.f, s1 = 0.f;
        #pragma unroll
        for (int j = 0; j < 8; j++) {
            sf[j].x = __expf(sf[j].x - mn0); s0 += sf[j].x;
            sf[j].y = __expf(sf[j].y - mn0); s0 += sf[j].y;
            sf[j].z = __expf(sf[j].z - mn1); s1 += sf[j].z;
            sf[j].w = __expf(sf[j].w - mn1); s1 += sf[j].w;
        }
        s0 += __shfl_xor_sync(0xffffffffu, s0, 1);
        s0 += __shfl_xor_sync(0xffffffffu, s0, 2);
        s1 += __shfl_xor_sync(0xffffffffu, s1, 1);
        s1 += __shfl_xor_sync(0xffffffffu, s1, 2);
        l0r = l0r*al0 + s0;  m0r = mn0;
        l1r = l1r*al1 + s1;  m1r = mn1;

        #pragma unroll
        for (int j = 0; j < 8; j++) {
            oacc[j].x *= al0; oacc[j].y *= al0;
            oacc[j].z *= al1; oacc[j].w *= al1;
        }

        // ---- P -> warp-private smem (tf32), no CTA barrier ----
        __syncwarp();                    // WAR: prev tile's P reads done
        #pragma unroll
        for (int j = 0; j < 8; j++) {
            *(uint2*)(Pw + g*PSTR + j*8 + 2*t4)     = make_uint2(tf32u(sf[j].x), tf32u(sf[j].y));
            *(uint2*)(Pw + (g+8)*PSTR + j*8 + 2*t4) = make_uint2(tf32u(sf[j].z), tf32u(sf[j].w));
        }
        __syncwarp();                    // RAW: P visible to whole warp

        // ---- O += P @ V ----
        #pragma unroll
        for (int k8 = 0; k8 < ATK; k8 += 8) {
            uint32_t af[4] = { Pw[g*PSTR + k8 + t4],     Pw[(g+8)*PSTR + k8 + t4],
                               Pw[g*PSTR + k8 + t4 + 4], Pw[(g+8)*PSTR + k8 + t4 + 4] };
            #pragma unroll
            for (int j = 0; j < 8; j++) {
                uint2 bv = *(const uint2*)(Vb + (j*8+g)*VTSTR + k8 + 2*t4);
                uint32_t bfr[2] = { bv.x, bv.y };
                mma_tf32(oacc[j], af, bfr);
            }
        }
    }

    // ---- normalize + write Y[b, q, h*64 + d] ----
    const float i0 = 1.f / l0r, i1 = 1.f / l1r;
    const int row0 = q0 + r0;
    #pragma unroll
    for (int j = 0; j < 8; j++) {
        int col = h*64 + j*8 + 2*t4;
        *(float2*)(Y + ((size_t)b*SS + row0)*EE + col) =
            make_float2(tf32f(oacc[j].x*i0), tf32f(oacc[j].y*i0));
        *(float2*)(Y + ((size_t)b*SS + row0 + 8)*EE + col) =
            make_float2(tf32f(oacc[j].z*i1), tf32f(oacc[j].w*i1));
    }
}

// ---------------- host launcher --------------------------------------------
extern "C" void kernel_launch(void* const* d_in, const int* in_sizes, int n_in,
                              void* d_out, int out_size)
{
    const float* x       = (const float*)d_in[0];
    const float* wq_down = (const float*)d_in[1];
    const float* wk_rope = (const float*)d_in[2];
    const float* wkv_down= (const float*)d_in[3];
    const float* wq_rope = (const float*)d_in[4];
    const float* wq_up   = (const float*)d_in[5];
    const float* wk_up   = (const float*)d_in[6];
    const float* wv_up   = (const float*)d_in[7];
    const float* wo      = (const float*)d_in[8];
    float* out = (float*)d_out;

    static float *p_xr=nullptr,*p_w768=nullptr,*p_wqp=nullptr,*p_wkvp=nullptr,*p_wor=nullptr,
                 *p_lat3=nullptr,*p_qc=nullptr,*p_kc=nullptr,*p_kr=nullptr,
                 *p_q=nullptr,*p_k=nullptr,*p_vt=nullptr,*p_y=nullptr;
    static bool inited = false;
    if (!inited) {
        cudaGetSymbolAddress((void**)&p_xr,   g_xr);
        cudaGetSymbolAddress((void**)&p_w768, g_w768);
        cudaGetSymbolAddress((void**)&p_wqp,  g_wqp);
        cudaGetSymbolAddress((void**)&p_wkvp, g_wkvp);
        cudaGetSymbolAddress((void**)&p_wor,  g_wor);
        cudaGetSymbolAddress((void**)&p_lat3, g_lat3);
        cudaGetSymbolAddress((void**)&p_qc,   g_qc);
        cudaGetSymbolAddress((void**)&p_kc,   g_kc);
        cudaGetSymbolAddress((void**)&p_kr,   g_kr);
        cudaGetSymbolAddress((void**)&p_q,    g_q);
        cudaGetSymbolAddress((void**)&p_k,    g_k);
        cudaGetSymbolAddress((void**)&p_vt,   g_vt);
        cudaGetSymbolAddress((void**)&p_y,    g_y);
        cudaFuncSetAttribute(attn_mma,
            cudaFuncAttributeMaxDynamicSharedMemorySize, (int)ATTN_SMEM);
        cudaFuncSetAttribute(mma_gemm<true>,
            cudaFuncAttributeMaxDynamicSharedMemorySize, (int)GEMM_SMEM);
        cudaFuncSetAttribute(mma_gemm<false>,
            cudaFuncAttributeMaxDynamicSharedMemorySize, (int)GEMM_SMEM);
        inited = true;
    }

    // stage 0: fused tf32 pre-rounding / packing (one launch)
    cvt_all_kernel<<<(1769472 + 255)/256, 256>>>(
        x, wq_down, wk_rope, wkv_down, wq_rope, wq_up, wk_up, wv_up, wo,
        p_xr, p_w768, p_wqp, p_wkvp, p_wor);

    // stage 1: fused down projections: lat3 = x @ [wq_down;wk_rope;wkv_down]^T
    mma_gemm<true><<<dim3(768/GBN, MM/GBM), 256, GEMM_SMEM>>>(
        p_xr, EE, p_w768, p_lat3, 768, 768, EE);

    // stage 2: up projections
    mma_gemm<false><<<dim3(2048/GBN, MM/GBM), 256, GEMM_SMEM>>>(
        p_lat3 + 0,   768, p_wqp,  p_qc, 2048, 2048, RR);   // qlat -> [qr|qn]
    mma_gemm<false><<<dim3(2048/GBN, MM/GBM), 256, GEMM_SMEM>>>(
        p_lat3 + 512, 768, p_wkvp, p_kc, 2048, 2048, RR);   // kv   -> [kn|vf]
    mma_gemm<false><<<dim3(1024/GBN, MM/GBM), 256, GEMM_SMEM>>>(
        p_lat3 + 256, 768, p_wkvp, p_kr, 1024, 1024, RR);   // klat -> kr

    // stage 3: head layout + RoPE (d-permuted; q pre-scaled by 1/sqrt(128))
    int nb = (BB*HH*SS*64 + 255) / 256;
    build_qk_kernel<<<nb, 256>>>(p_qc, 2048, p_qc + 1024, 2048, p_q, 0.08838834764831845f);
    build_qk_kernel<<<nb, 256>>>(p_kr, 1024, p_kc,        2048, p_k, 1.0f);
    build_vt_kernel<<<dim3(2, SS/32, BB*HH), dim3(32, 8)>>>(p_kc + 1024, 2048, p_vt);

    // stage 4: causal flash attention on tensor cores
    attn_mma<<<dim3(SS/ATQ, BB*HH), 256, ATTN_SMEM>>>(p_q, p_k, p_vt, p_y);

    // stage 5: output projection
    mma_gemm<false><<<dim3(EE/GBN, MM/GBM), 256, GEMM_SMEM>>>(
        p_y, EE, p_wor, out, EE, EE, EE);
}

// round 14
// speedup vs baseline: 4.1981x; 1.1135x over previous
#include <cuda_runtime.h>
#include <cuda_bf16.h>
#include <cstdint>

// Problem constants
#define BB 2
#define SS 2048
#define EE 1024
#define RR 256
#define HH 16
#define MM (BB*SS)     // 4096

// ---------------- scratch (device globals; no allocation allowed) ----------
__device__ float g_xr  [MM*EE];          // tf32-rounded x
__device__ float g_w768[768*EE];         // packed [wq_down; wk_rope; wkv_down]
__device__ float g_wqp [2048*RR];        // packed [wq_rope; wq_up]
__device__ float g_wkvp[2048*RR];        // packed [wk_up; wv_up]
__device__ float g_wor [EE*EE];          // rounded wo
__device__ float g_lat3[MM*768];         // [qlat | klat | kv]
__device__ float g_qc  [MM*2048];        // [qr | qn]
__device__ float g_kc  [MM*2048];        // [kn | vf]
__device__ float g_kr  [MM*EE];
__device__ float g_q   [BB*HH*SS*128];   // d-permuted within 8-groups
__device__ float g_k   [BB*HH*SS*128];   // d-permuted within 8-groups
__device__ float g_vt  [BB*HH*64*SS];    // [bh][d][s], s permuted within 8-groups
__device__ float g_y   [MM*EE];

// ---------------- tf32 + cp.async helpers ----------------------------------
__device__ __forceinline__ uint32_t tf32u(float x) {
    uint32_t r; asm("cvt.rna.tf32.f32 %0, %1;" : "=r"(r) : "f"(x)); return r;
}
__device__ __forceinline__ float tf32f(float x) {
    return __uint_as_float(tf32u(x));
}
__device__ __forceinline__ float ex2f(float x) {
    float r; asm("ex2.approx.ftz.f32 %0, %1;" : "=f"(r) : "f"(x)); return r;
}
__device__ __forceinline__ void mma_tf32(float4& c, const uint32_t* a, const uint32_t* b) {
    asm volatile("mma.sync.aligned.m16n8k8.row.col.f32.tf32.tf32.f32 "
        "{%0,%1,%2,%3}, {%4,%5,%6,%7}, {%8,%9}, {%0,%1,%2,%3};\n"
        : "+f"(c.x), "+f"(c.y), "+f"(c.z), "+f"(c.w)
        : "r"(a[0]), "r"(a[1]), "r"(a[2]), "r"(a[3]), "r"(b[0]), "r"(b[1]));
}
__device__ __forceinline__ void cp16(void* smem_dst, const void* gptr) {
    uint32_t sa = (uint32_t)__cvta_generic_to_shared(smem_dst);
    asm volatile("cp.async.cg.shared.global [%0], [%1], 16;\n" :: "r"(sa), "l"(gptr));
}
#define CP_COMMIT() asm volatile("cp.async.commit_group;\n" ::: "memory")
#define CP_WAIT(n)  asm volatile("cp.async.wait_group %0;\n" :: "n"(n) : "memory")

// ---------------- fused tf32 rounding of all inputs ------------------------
__global__ void cvt_all_kernel(
    const float* __restrict__ x,
    const float* __restrict__ w1, const float* __restrict__ w2, const float* __restrict__ w3,
    const float* __restrict__ w4, const float* __restrict__ w5, const float* __restrict__ w6,
    const float* __restrict__ w7, const float* __restrict__ wo,
    float* __restrict__ xr, float* __restrict__ w768,
    float* __restrict__ wqp, float* __restrict__ wkvp, float* __restrict__ wor)
{
    int i = blockIdx.x * blockDim.x + threadIdx.x;
    const float4* s; float4* d; int off;
    if (i < 1048576)      { s = (const float4*)x;  d = (float4*)xr;   off = i; }
    else if (i < 1114112) { s = (const float4*)w1; d = (float4*)w768; off = i - 1048576; }
    else if (i < 1179648) { s = (const float4*)w2; d = (float4*)(w768 + RR*EE); off = i - 1114112; }
    else if (i < 1245184) { s = (const float4*)w3; d = (float4*)(w768 + 2*RR*EE); off = i - 1179648; }
    else if (i < 1310720) { s = (const float4*)w4; d = (float4*)wqp; off = i - 1245184; }
    else if (i < 1376256) { s = (const float4*)w5; d = (float4*)(wqp + EE*RR); off = i - 1310720; }
    else if (i < 1441792) { s = (const float4*)w6; d = (float4*)wkvp; off = i - 1376256; }
    else if (i < 1507328) { s = (const float4*)w7; d = (float4*)(wkvp + EE*RR); off = i - 1441792; }
    else if (i < 1769472) { s = (const float4*)wo; d = (float4*)wor; off = i - 1507328; }
    else return;
    float4 v = s[off];
    v.x = tf32f(v.x); v.y = tf32f(v.y); v.z = tf32f(v.z); v.w = tf32f(v.w);
    d[off] = v;
}

// ---------------- tf32 tensor-core GEMM (cp.async double-buffered) ---------
#define GBM 128
#define GBN 128
#define GBK 32
#define GBKP 36
#define GEMM_SMEM (2*(GBM*GBKP + GBN*GBKP)*4)

template<bool ROUND>
__device__ __forceinline__ void gemm_body(
    const float* __restrict__ A, int lda,
    const float* __restrict__ W,
    float* __restrict__ C, int ldc, int K, int m0, int n0)
{
    extern __shared__ uint32_t gsm[];
    uint32_t* As = gsm;
    uint32_t* Ws = gsm + 2*GBM*GBKP;

    const int tid  = threadIdx.x;
    const int wid  = tid >> 5, lane = tid & 31;
    const int g    = lane >> 2, t4 = lane & 3;
    const int wr   = wid >> 2, wc = wid & 3;
    const int m0w  = wr * 64, n0w = wc * 32;

    float4 acc[4][4];
    #pragma unroll
    for (int m = 0; m < 4; m++)
        #pragma unroll
        for (int n = 0; n < 4; n++) acc[m][n] = make_float4(0.f,0.f,0.f,0.f);

    const int ntiles = K / GBK;
    {
        #pragma unroll
        for (int idx = tid; idx < GBM*8; idx += 256) {
            int row = idx >> 3, seg = idx & 7;
            cp16(As + row*GBKP + seg*4, A + (size_t)(m0+row)*lda + seg*4);
        }
        #pragma unroll
        for (int idx = tid; idx < GBN*8; idx += 256) {
            int row = idx >> 3, seg = idx & 7;
            cp16(Ws + row*GBKP + seg*4, W + (size_t)(n0+row)*K + seg*4);
        }
        CP_COMMIT();
    }

    for (int t = 0; t < ntiles; t++) {
        __syncthreads();
        if (t + 1 < ntiles) {
            int kt = (t+1)*GBK;
            uint32_t* Ad = As + ((t+1)&1)*GBM*GBKP;
            uint32_t* Wd = Ws + ((t+1)&1)*GBN*GBKP;
            #pragma unroll
            for (int idx = tid; idx < GBM*8; idx += 256) {
                int row = idx >> 3, seg = idx & 7;
                cp16(Ad + row*GBKP + seg*4, A + (size_t)(m0+row)*lda + kt + seg*4);
            }
            #pragma unroll
            for (int idx = tid; idx < GBN*8; idx += 256) {
                int row = idx >> 3, seg = idx & 7;
                cp16(Wd + row*GBKP + seg*4, W + (size_t)(n0+row)*K + kt + seg*4);
            }
            CP_COMMIT();
            CP_WAIT(1);
        } else {
            CP_WAIT(0);
        }
        __syncthreads();

        const uint32_t* Ab = As + (t&1)*GBM*GBKP;
        const uint32_t* Wb = Ws + (t&1)*GBN*GBKP;
        #pragma unroll
        for (int k8 = 0; k8 < GBK; k8 += 8) {
            uint32_t bf[4][2];
            #pragma unroll
            for (int n = 0; n < 4; n++) {
                const uint32_t* bp = Wb + (n0w + n*8 + g)*GBKP + k8 + t4;
                bf[n][0] = bp[0];
                bf[n][1] = bp[4];
            }
            #pragma unroll
            for (int m = 0; m < 4; m++) {
                const uint32_t* ap = Ab + (m0w + m*16 + g)*GBKP + k8 + t4;
                uint32_t af[4] = { ap[0], ap[8*GBKP], ap[4], ap[8*GBKP + 4] };
                #pragma unroll
                for (int n = 0; n < 4; n++)
                    mma_tf32(acc[m][n], af, bf[n]);
            }
        }
    }

    #pragma unroll
    for (int m = 0; m < 4; m++) {
        #pragma unroll
        for (int n = 0; n < 4; n++) {
            int row = m0 + m0w + m*16 + g;
            int col = n0 + n0w + n*8 + 2*t4;
            float4 v = acc[m][n];
            if (ROUND) { v.x = tf32f(v.x); v.y = tf32f(v.y); v.z = tf32f(v.z); v.w = tf32f(v.w); }
            *(float2*)(C + (size_t)row*ldc + col)     = make_float2(v.x, v.y);
            *(float2*)(C + (size_t)(row+8)*ldc + col) = make_float2(v.z, v.w);
        }
    }
}

template<bool ROUND>
__global__ void __launch_bounds__(256, 2) mma_gemm(
    const float* __restrict__ A, int lda,
    const float* __restrict__ W,
    float* __restrict__ C, int ldc, int N, int K)
{
    gemm_body<ROUND>(A, lda, W, C, ldc, K, blockIdx.y*GBM, blockIdx.x*GBN);
}

// grouped stage-2: bx 0..15 -> qc, 16..31 -> kc, 32..39 -> kr
__global__ void __launch_bounds__(256, 2) mma_gemm_s2(
    const float* __restrict__ lat3,
    const float* __restrict__ wqp, const float* __restrict__ wkvp,
    float* __restrict__ qc, float* __restrict__ kc, float* __restrict__ kr)
{
    int bx = blockIdx.x;
    const float* A; const float* W; float* C; int ldc, n0;
    if (bx < 16)      { A = lat3;        W = wqp;  C = qc; ldc = 2048; n0 = bx*128; }
    else if (bx < 32) { A = lat3 + 512;  W = wkvp; C = kc; ldc = 2048; n0 = (bx-16)*128; }
    else              { A = lat3 + 256;  W = wkvp; C = kr; ldc = 1024; n0 = (bx-32)*128; }
    gemm_body<false>(A, 768, W, C, ldc, RR, blockIdx.y*GBM, n0);
}

// --------- build q/k: rope||up -> [B,H,S,128], d permuted within 8-groups --
__global__ void build_qk_kernel(const float* __restrict__ ropein, int ldr,
                                const float* __restrict__ upin, int ldu,
                                float* __restrict__ outp, float scale)
{
    int idx = blockIdx.x * blockDim.x + threadIdx.x;   // over B*H*S*64
    if (idx >= BB*HH*SS*64) return;
    int d = idx & 63;
    int s = (idx >> 6) & (SS-1);
    int h = (idx >> 17) & (HH-1);
    int b = idx >> 21;
    const size_t rbase = (size_t)(b*SS + s)*ldr + h*64;
    const size_t ubase = (size_t)(b*SS + s)*ldu + h*64;
    float x1 = ropein[rbase + d];
    float rot; int fi;
    if (d < 32) { rot = -ropein[rbase + d + 32]; fi = d; }
    else        { rot =  ropein[rbase + d - 32]; fi = d - 32; }
    float inv = __powf(10000.0f, -(float)(2*fi) * (1.0f/64.0f));
    float ang = (float)s * inv;
    float sn, cs; sincosf(ang, &sn, &cs);
    float val = fmaf(x1, cs, rot*sn);
    const int ob = ((b*HH + h)*SS + s)*128;
    const int dp = (d & ~7) | (2*(d & 3) + ((d >> 2) & 1));   // LDS.64 perm
    outp[ob + dp]      = tf32f(val * scale);
    outp[ob + 64 + dp] = tf32f(upin[ubase + d] * scale);
}

// --------- build Vt: [bh][d][s], s permuted within 8-groups ----------------
__global__ void build_vt_kernel(const float* __restrict__ vf, int ldv,
                                float* __restrict__ vt)
{
    __shared__ float tile[32][33];
    const int bh = blockIdx.z, h = bh & 15, b = bh >> 4;
    const int d0 = blockIdx.x * 32, s0 = blockIdx.y * 32;
    const int tx = threadIdx.x, ty = threadIdx.y;
    #pragma unroll
    for (int i = 0; i < 4; i++) {
        int sl = ty + i*8;
        tile[sl][tx] = vf[(size_t)(b*SS + s0 + sl)*ldv + h*64 + d0 + tx];
    }
    __syncthreads();
    const int sp = (tx & ~7) | (2*(tx & 3) + ((tx >> 2) & 1));
    #pragma unroll
    for (int i = 0; i < 4; i++) {
        int dl = ty + i*8;
        vt[((size_t)bh*64 + d0 + dl)*SS + s0 + sp] = tf32f(tile[tx][dl]);
    }
}

// ---------------- causal flash attention, tf32 mma, cp.async ----------------
// Q,K: [B,H,S,128] tf32 bits, d-permuted (Q pre-scaled by log2e/sqrt(128));
// Vt: [bh][64][S] s-permuted. CTA: 64 q-rows x one (b,h); 4 warps, each 16 rows.
// Q fragments live in registers; K double-buffered; V single-buffered in-tile.
#define ATQ 64
#define ATK 64
#define KSTR 136
#define VTSTR 72
#define PSTR 72
#define ATTN_SMEM ((2*ATK*KSTR + 64*VTSTR + ATQ*PSTR) * 4)

__global__ void __launch_bounds__(128) attn_mma(
    const float* __restrict__ Q, const float* __restrict__ Kg,
    const float* __restrict__ Vtg, float* __restrict__ Y)
{
    extern __shared__ __align__(16) uint32_t smu[];
    uint32_t* Ks = smu;                    // [2][64][KSTR]
    uint32_t* Vt = Ks + 2*ATK*KSTR;        // [64][VTSTR]
    uint32_t* Ps = Vt + 64*VTSTR;          // [64][PSTR] warp-private slices

    const int tid = threadIdx.x;
    const int lane = tid & 31, wid = tid >> 5;
    const int g = lane >> 2, t4 = lane & 3;
    const int r0 = wid*16 + g;
    const int q0 = ((int)gridDim.x - 1 - (int)blockIdx.x) * ATQ;  // heavy first
    const int bh = blockIdx.y, b = bh >> 4, h = bh & 15;

    const float* qbase  = Q + ((size_t)bh*SS + q0)*128;
    const float* kbase  = Kg + (size_t)bh*SS*128;
    const float* vtbase = Vtg + (size_t)bh*64*SS;

    // prologue: stage Q tile into Ks buffer 1, K(0) into buffer 0
    uint32_t* Qstage = Ks + ATK*KSTR;
    #pragma unroll
    for (int idx = tid; idx < ATQ*32; idx += 128) {
        int row = idx >> 5, seg = idx & 31;
        cp16(Qstage + row*KSTR + seg*4, qbase + row*128 + seg*4);
    }
    CP_COMMIT();                                         // group: Q
    #pragma unroll
    for (int idx = tid; idx < ATK*32; idx += 128) {
        int row = idx >> 5, seg = idx & 31;
        cp16(Ks + row*KSTR + seg*4, kbase + (size_t)row*128 + seg*4);
    }
    CP_COMMIT();                                         // group: K(0)
    CP_WAIT(1);                                          // Q ready
    __syncthreads();

    // Q fragments -> registers (held for the whole kernel)
    uint32_t qf[16][4];
    #pragma unroll
    for (int i = 0; i < 16; i++) {
        uint2 alo = *(const uint2*)(Qstage + r0*KSTR + i*8 + 2*t4);
        uint2 ahi = *(const uint2*)(Qstage + (r0+8)*KSTR + i*8 + 2*t4);
        qf[i][0] = alo.x; qf[i][1] = ahi.x; qf[i][2] = alo.y; qf[i][3] = ahi.y;
    }

    float4 oacc[8];
    #pragma unroll
    for (int j = 0; j < 8; j++) oacc[j] = make_float4(0.f,0.f,0.f,0.f);
    float m0r = -1e30f, m1r = -1e30f, l0r = 0.f, l1r = 0.f;
    uint32_t* Pw = Ps + wid*16*PSTR;

    const int ntiles = q0/ATK + 1;

    for (int t = 0; t < ntiles; t++) {
        __syncthreads();          // B1: V(t-1)/P consumed; Qstage reads done (t=0)

        // issue V(t) into the single V buffer
        #pragma unroll
        for (int idx = tid; idx < 64*16; idx += 128) {
            int row = idx >> 4, seg = idx & 15;
            cp16(Vt + row*VTSTR + seg*4, vtbase + (size_t)row*SS + t*ATK + seg*4);
        }
        CP_COMMIT();                                     // group: V(t)
        if (t + 1 < ntiles) {
            int k0n = (t+1)*ATK;
            uint32_t* Kd = Ks + ((t+1)&1)*ATK*KSTR;
            #pragma unroll
            for (int idx = tid; idx < ATK*32; idx += 128) {
                int row = idx >> 5, seg = idx & 31;
                cp16(Kd + row*KSTR + seg*4, kbase + (size_t)(k0n+row)*128 + seg*4);
            }
            CP_COMMIT();                                 // group: K(t+1)
            CP_WAIT(2);                                  // K(t) ready
        } else {
            CP_WAIT(1);                                  // K(t) ready
        }
        __syncthreads();          // B2: K(t) visible

        const int k0 = t*ATK;
        const uint32_t* Kb = Ks + (t&1)*ATK*KSTR;

        // ---- S = Q @ K^T : warp computes 16 rows x 64 cols ----
        float4 sf[8];
        #pragma unroll
        for (int j = 0; j < 8; j++) sf[j] = make_float4(0.f,0.f,0.f,0.f);

        #pragma unroll
        for (int i = 0; i < 16; i++) {
            #pragma unroll
            for (int j = 0; j < 8; j++) {
                uint2 bv = *(const uint2*)(Kb + (j*8+g)*KSTR + i*8 + 2*t4);
                uint32_t bfr[2] = { bv.x, bv.y };
                mma_tf32(sf[j], qf[i], bfr);
            }
        }

        // ---- causal mask (register; scores are in log2 units) ----
        if (k0 + ATK - 1 > q0 + wid*16) {
            const int qr0 = q0 + r0, qr1 = qr0 + 8;
            #pragma unroll
            for (int j = 0; j < 8; j++) {
                int c0 = k0 + j*8 + 2*t4, c1 = c0 + 1;
                if (c0 > qr0) sf[j].x = -1e30f;
                if (c1 > qr0) sf[j].y = -1e30f;
                if (c0 > qr1) sf[j].z = -1e30f;
                if (c1 > qr1) sf[j].w = -1e30f;
            }
        }

        // ---- warp-local online softmax (base-2) ----
        float mx0 = -1e30f, mx1 = -1e30f;
        #pragma unroll
        for (int j = 0; j < 8; j++) {
            mx0 = fmaxf(mx0, fmaxf(sf[j].x, sf[j].y));
            mx1 = fmaxf(mx1, fmaxf(sf[j].z, sf[j].w));
        }
        mx0 = fmaxf(mx0, __shfl_xor_sync(0xffffffffu, mx0, 1));
        mx0 = fmaxf(mx0, __shfl_xor_sync(0xffffffffu, mx0, 2));
        mx1 = fmaxf(mx1, __shfl_xor_sync(0xffffffffu, mx1, 1));
        mx1 = fmaxf(mx1, __shfl_xor_sync(0xffffffffu, mx1, 2));

        float mn0 = fmaxf(m0r, mx0), mn1 = fmaxf(m1r, mx1);
        float al0 = ex2f(m0r - mn0), al1 = ex2f(m1r - mn1);
        float s0 = 0.f, s1 = 0.f;
        #pragma unroll
        for (int j = 0; j < 8; j++) {
            sf[j].x = ex2f(sf[j].x - mn0); s0 += sf[j].x;
            sf[j].y = ex2f(sf[j].y - mn0); s0 += sf[j].y;
            sf[j].z = ex2f(sf[j].z - mn1); s1 += sf[j].z;
            sf[j].w = ex2f(sf[j].w - mn1); s1 += sf[j].w;
        }
        s0 += __shfl_xor_sync(0xffffffffu, s0, 1);
        s0 += __shfl_xor_sync(0xffffffffu, s0, 2);
        s1 += __shfl_xor_sync(0xffffffffu, s1, 1);
        s1 += __shfl_xor_sync(0xffffffffu, s1, 2);
        l0r = l0r*al0 + s0;  m0r = mn0;
        l1r = l1r*al1 + s1;  m1r = mn1;

        #pragma unroll
        for (int j = 0; j < 8; j++) {
            oacc[j].x *= al0; oacc[j].y *= al0;
            oacc[j].z *= al1; oacc[j].w *= al1;
        }

        // ---- P -> warp-private smem (tf32), no CTA barrier ----
        __syncwarp();
        #pragma unroll
        for (int j = 0; j < 8; j++) {
            *(uint2*)(Pw + g*PSTR + j*8 + 2*t4)     = make_uint2(tf32u(sf[j].x), tf32u(sf[j].y));
            *(uint2*)(Pw + (g+8)*PSTR + j*8 + 2*t4) = make_uint2(tf32u(sf[j].z), tf32u(sf[j].w));
        }
        __syncwarp();

        // ---- wait V(t), then O += P @ V ----
        if (t + 1 < ntiles) CP_WAIT(1); else CP_WAIT(0);
        __syncthreads();          // B3: V(t) visible

        #pragma unroll
        for (int k8 = 0; k8 < ATK; k8 += 8) {
            uint32_t af[4] = { Pw[g*PSTR + k8 + t4],     Pw[(g+8)*PSTR + k8 + t4],
                               Pw[g*PSTR + k8 + t4 + 4], Pw[(g+8)*PSTR + k8 + t4 + 4] };
            #pragma unroll
            for (int j = 0; j < 8; j++) {
                uint2 bv = *(const uint2*)(Vt + (j*8+g)*VTSTR + k8 + 2*t4);
                uint32_t bfr[2] = { bv.x, bv.y };
                mma_tf32(oacc[j], af, bfr);
            }
        }
    }

    // ---- normalize + write Y[b, q, h*64 + d] ----
    const float i0 = 1.f / l0r, i1 = 1.f / l1r;
    const int row0 = q0 + r0;
    #pragma unroll
    for (int j = 0; j < 8; j++) {
        int col = h*64 + j*8 + 2*t4;
        *(float2*)(Y + ((size_t)b*SS + row0)*EE + col) =
            make_float2(tf32f(oacc[j].x*i0), tf32f(oacc[j].y*i0));
        *(float2*)(Y + ((size_t)b*SS + row0 + 8)*EE + col) =
            make_float2(tf32f(oacc[j].z*i1), tf32f(oacc[j].w*i1));
    }
}

// ---------------- host launcher --------------------------------------------
extern "C" void kernel_launch(void* const* d_in, const int* in_sizes, int n_in,
                              void* d_out, int out_size)
{
    const float* x       = (const float*)d_in[0];
    const float* wq_down = (const float*)d_in[1];
    const float* wk_rope = (const float*)d_in[2];
    const float* wkv_down= (const float*)d_in[3];
    const float* wq_rope = (const float*)d_in[4];
    const float* wq_up   = (const float*)d_in[5];
    const float* wk_up   = (const float*)d_in[6];
    const float* wv_up   = (const float*)d_in[7];
    const float* wo      = (const float*)d_in[8];
    float* out = (float*)d_out;

    static float *p_xr=nullptr,*p_w768=nullptr,*p_wqp=nullptr,*p_wkvp=nullptr,*p_wor=nullptr,
                 *p_lat3=nullptr,*p_qc=nullptr,*p_kc=nullptr,*p_kr=nullptr,
                 *p_q=nullptr,*p_k=nullptr,*p_vt=nullptr,*p_y=nullptr;
    static bool inited = false;
    if (!inited) {
        cudaGetSymbolAddress((void**)&p_xr,   g_xr);
        cudaGetSymbolAddress((void**)&p_w768, g_w768);
        cudaGetSymbolAddress((void**)&p_wqp,  g_wqp);
        cudaGetSymbolAddress((void**)&p_wkvp, g_wkvp);
        cudaGetSymbolAddress((void**)&p_wor,  g_wor);
        cudaGetSymbolAddress((void**)&p_lat3, g_lat3);
        cudaGetSymbolAddress((void**)&p_qc,   g_qc);
        cudaGetSymbolAddress((void**)&p_kc,   g_kc);
        cudaGetSymbolAddress((void**)&p_kr,   g_kr);
        cudaGetSymbolAddress((void**)&p_q,    g_q);
        cudaGetSymbolAddress((void**)&p_k,    g_k);
        cudaGetSymbolAddress((void**)&p_vt,   g_vt);
        cudaGetSymbolAddress((void**)&p_y,    g_y);
        cudaFuncSetAttribute(attn_mma,
            cudaFuncAttributeMaxDynamicSharedMemorySize, (int)ATTN_SMEM);
        cudaFuncSetAttribute(mma_gemm<true>,
            cudaFuncAttributeMaxDynamicSharedMemorySize, (int)GEMM_SMEM);
        cudaFuncSetAttribute(mma_gemm<false>,
            cudaFuncAttributeMaxDynamicSharedMemorySize, (int)GEMM_SMEM);
        cudaFuncSetAttribute(mma_gemm_s2,
            cudaFuncAttributeMaxDynamicSharedMemorySize, (int)GEMM_SMEM);
        inited = true;
    }

    // stage 0: fused tf32 pre-rounding / packing (one launch)
    cvt_all_kernel<<<(1769472 + 255)/256, 256>>>(
        x, wq_down, wk_rope, wkv_down, wq_rope, wq_up, wk_up, wv_up, wo,
        p_xr, p_w768, p_wqp, p_wkvp, p_wor);

    // stage 1: fused down projections: lat3 = x @ [wq_down;wk_rope;wkv_down]^T
    mma_gemm<true><<<dim3(768/GBN, MM/GBM), 256, GEMM_SMEM>>>(
        p_xr, EE, p_w768, p_lat3, 768, 768, EE);

    // stage 2: grouped up projections (qc | kc | kr) in one launch
    mma_gemm_s2<<<dim3(40, MM/GBM), 256, GEMM_SMEM>>>(
        p_lat3, p_wqp, p_wkvp, p_qc, p_kc, p_kr);

    // stage 3: head layout + RoPE (d-permuted; q pre-scaled by log2e/sqrt(128))
    int nb = (BB*HH*SS*64 + 255) / 256;
    build_qk_kernel<<<nb, 256>>>(p_qc, 2048, p_qc + 1024, 2048, p_q,
                                 0.08838834764831845f * 1.4426950408889634f);
    build_qk_kernel<<<nb, 256>>>(p_kr, 1024, p_kc,        2048, p_k, 1.0f);
    build_vt_kernel<<<dim3(2, SS/32, BB*HH), dim3(32, 8)>>>(p_kc + 1024, 2048, p_vt);

    // stage 4: causal flash attention on tensor cores
    attn_mma<<<dim3(SS/ATQ, BB*HH), 128, ATTN_SMEM>>>(p_q, p_k, p_vt, p_y);

    // stage 5: output projection
    mma_gemm<false><<<dim3(EE/GBN, MM/GBM), 256, GEMM_SMEM>>>(
        p_y, EE, p_wor, out, EE, EE, EE);
}

// round 16
// speedup vs baseline: 7.5487x; 1.7981x over previous
#include <cuda_runtime.h>
#include <cuda_bf16.h>
#include <cuda_fp16.h>
#include <cstdint>

// Problem constants
#define BB 2
#define SS 2048
#define EE 1024
#define RR 256
#define HH 16
#define MM (BB*SS)     // 4096

// ---------------- scratch (device globals; no allocation allowed) ----------
__device__ __align__(16) __half g_xh  [MM*EE];     // fp16 perm-packed x
__device__ __align__(16) __half g_w768[768*EE];    // packed [wq_down;wk_rope;wkv_down]
__device__ __align__(16) __half g_wqp [2048*RR];   // packed [wq_rope; wq_up]
__device__ __align__(16) __half g_wkvp[2048*RR];   // packed [wk_up; wv_up]
__device__ __align__(16) __half g_woh [EE*EE];     // wo fp16 perm
__device__ __align__(16) __half g_lat3[MM*768];    // [qlat|klat|kv] fp16 perm
__device__ float g_qc  [MM*2048];                  // [qr | qn]  (f32 natural)
__device__ float g_kc  [MM*2048];                  // [kn | vf]
__device__ float g_kr  [MM*EE];
__device__ __align__(16) __half g_q   [BB*HH*SS*128];  // fp16, pair-permuted
__device__ __align__(16) __half g_k   [BB*HH*SS*128];
__device__ __align__(16) __half g_vt  [BB*HH*64*SS];   // [bh][d][s], s pair-perm
__device__ __align__(16) __half g_y   [MM*EE];         // fp16 perm-packed

// ---------------- helpers ---------------------------------------------------
__device__ __forceinline__ float ex2f(float x) {
    float r; asm("ex2.approx.ftz.f32 %0, %1;" : "=f"(r) : "f"(x)); return r;
}
__device__ __forceinline__ uint32_t h2u(float a, float b) {
    __half2 h = __floats2half2_rn(a, b);
    return *reinterpret_cast<uint32_t*>(&h);
}
// pair-permuted half2 index for even element c (perm within 16-elem groups)
__device__ __forceinline__ int pp_h2(int c) {
    int p = (c >> 1) & 7;
    return ((c >> 4) << 3) + 2*(p & 3) + (p >> 2);
}
// element-level permuted position
__device__ __forceinline__ int pp_el(int d) {
    int p = (d >> 1) & 7;
    return (d & ~15) + 2*(2*(p & 3) + (p >> 2)) + (d & 1);
}
// D += A(16x16) * B(16x8), fp16 inputs, fp32 accumulate
__device__ __forceinline__ void mma_f16(float4& c, const uint32_t* a, const uint32_t* b) {
    asm volatile("mma.sync.aligned.m16n8k16.row.col.f32.f16.f16.f32 "
        "{%0,%1,%2,%3}, {%4,%5,%6,%7}, {%8,%9}, {%0,%1,%2,%3};\n"
        : "+f"(c.x), "+f"(c.y), "+f"(c.z), "+f"(c.w)
        : "r"(a[0]), "r"(a[1]), "r"(a[2]), "r"(a[3]), "r"(b[0]), "r"(b[1]));
}
__device__ __forceinline__ void cp16(void* smem_dst, const void* gptr) {
    uint32_t sa = (uint32_t)__cvta_generic_to_shared(smem_dst);
    asm volatile("cp.async.cg.shared.global [%0], [%1], 16;\n" :: "r"(sa), "l"(gptr));
}
#define CP_COMMIT() asm volatile("cp.async.commit_group;\n" ::: "memory")
#define CP_WAIT(n)  asm volatile("cp.async.wait_group %0;\n" :: "n"(n) : "memory")

// ---------------- fused fp16 conversion + pair-perm packing ----------------
__global__ void cvt_all_kernel(
    const float* __restrict__ x,
    const float* __restrict__ w1, const float* __restrict__ w2, const float* __restrict__ w3,
    const float* __restrict__ w4, const float* __restrict__ w5, const float* __restrict__ w6,
    const float* __restrict__ w7, const float* __restrict__ wo,
    __half* __restrict__ xh, __half* __restrict__ w768,
    __half* __restrict__ wqp, __half* __restrict__ wkvp, __half* __restrict__ woh)
{
    int i = blockIdx.x * blockDim.x + threadIdx.x;
    const float4* s; __half* d; int off;
    if (i < 1048576)      { s = (const float4*)x;  d = xh;   off = i; }
    else if (i < 1114112) { s = (const float4*)w1; d = w768; off = i - 1048576; }
    else if (i < 1179648) { s = (const float4*)w2; d = w768 + RR*EE; off = i - 1114112; }
    else if (i < 1245184) { s = (const float4*)w3; d = w768 + 2*RR*EE; off = i - 1179648; }
    else if (i < 1310720) { s = (const float4*)w4; d = wqp; off = i - 1245184; }
    else if (i < 1376256) { s = (const float4*)w5; d = wqp + EE*RR; off = i - 1310720; }
    else if (i < 1441792) { s = (const float4*)w6; d = wkvp; off = i - 1376256; }
    else if (i < 1507328) { s = (const float4*)w7; d = wkvp + EE*RR; off = i - 1441792; }
    else if (i < 1769472) { s = (const float4*)wo; d = woh; off = i - 1507328; }
    else return;
    float4 v = s[off];
    uint32_t* d32 = (uint32_t*)d;
    int e = off * 4;                 // rows are multiples of 16 -> flat perm ok
    d32[pp_h2(e)]     = h2u(v.x, v.y);
    d32[pp_h2(e + 2)] = h2u(v.z, v.w);
}

// ---------------- fp16 tensor-core GEMM (cp.async double-buffered) ---------
// C[M,N] = A[M,K] * W[N,K]^T ; A,W fp16 pair-permuted along K. 256 thr, 2x4.
#define GBM 128
#define GBN 128
#define GBK 64
#define GBKP 40                       // row stride in half2 (32 data + 8 pad)
#define GEMM_SMEM (2*(GBM + GBN)*GBKP*4)

// EPI: 0 = f32 natural, 1 = fp16 pair-perm packed
template<int EPI>
__device__ __forceinline__ void gemm_body(
    const __half* __restrict__ A, int lda,
    const __half* __restrict__ W,
    void* __restrict__ C, int ldc, int K, int m0, int n0)
{
    extern __shared__ uint32_t gsm[];
    uint32_t* As = gsm;                       // [2][GBM][GBKP]
    uint32_t* Ws = gsm + 2*GBM*GBKP;          // [2][GBN][GBKP]

    const int tid  = threadIdx.x;
    const int wid  = tid >> 5, lane = tid & 31;
    const int g    = lane >> 2, t4 = lane & 3;
    const int wr   = wid >> 2, wc = wid & 3;   // 2 x 4 warp grid (WM=64, WN=32)
    const int m0w  = wr * 64, n0w = wc * 32;

    float4 acc[4][4];
    #pragma unroll
    for (int m = 0; m < 4; m++)
        #pragma unroll
        for (int n = 0; n < 4; n++) acc[m][n] = make_float4(0.f,0.f,0.f,0.f);

    const int ntiles = K / GBK;
    {
        #pragma unroll
        for (int idx = tid; idx < GBM*8; idx += 256) {
            int row = idx >> 3, seg = idx & 7;
            cp16(As + row*GBKP + seg*4, A + (size_t)(m0+row)*lda + seg*8);
        }
        #pragma unroll
        for (int idx = tid; idx < GBN*8; idx += 256) {
            int row = idx >> 3, seg = idx & 7;
            cp16(Ws + row*GBKP + seg*4, W + (size_t)(n0+row)*K + seg*8);
        }
        CP_COMMIT();
    }

    for (int t = 0; t < ntiles; t++) {
        __syncthreads();
        if (t + 1 < ntiles) {
            int kt = (t+1)*GBK;
            uint32_t* Ad = As + ((t+1)&1)*GBM*GBKP;
            uint32_t* Wd = Ws + ((t+1)&1)*GBN*GBKP;
            #pragma unroll
            for (int idx = tid; idx < GBM*8; idx += 256) {
                int row = idx >> 3, seg = idx & 7;
                cp16(Ad + row*GBKP + seg*4, A + (size_t)(m0+row)*lda + kt + seg*8);
            }
            #pragma unroll
            for (int idx = tid; idx < GBN*8; idx += 256) {
                int row = idx >> 3, seg = idx & 7;
                cp16(Wd + row*GBKP + seg*4, W + (size_t)(n0+row)*K + kt + seg*8);
            }
            CP_COMMIT();
            CP_WAIT(1);
        } else {
            CP_WAIT(0);
        }
        __syncthreads();

        const uint32_t* Ab = As + (t&1)*GBM*GBKP;
        const uint32_t* Wb = Ws + (t&1)*GBN*GBKP;
        #pragma unroll
        for (int grp = 0; grp < GBK/16; grp++) {
            uint2 bf[4];
            #pragma unroll
            for (int n = 0; n < 4; n++)
                bf[n] = *(const uint2*)(Wb + (n0w + n*8 + g)*GBKP + grp*8 + 2*t4);
            #pragma unroll
            for (int m = 0; m < 4; m++) {
                uint2 lo = *(const uint2*)(Ab + (m0w + m*16 + g)*GBKP + grp*8 + 2*t4);
                uint2 hi = *(const uint2*)(Ab + (m0w + m*16 + g + 8)*GBKP + grp*8 + 2*t4);
                uint32_t af[4] = { lo.x, hi.x, lo.y, hi.y };
                #pragma unroll
                for (int n = 0; n < 4; n++)
                    mma_f16(acc[m][n], af, (const uint32_t*)&bf[n]);
            }
        }
    }

    #pragma unroll
    for (int m = 0; m < 4; m++) {
        #pragma unroll
        for (int n = 0; n < 4; n++) {
            int row = m0 + m0w + m*16 + g;
            int col = n0 + n0w + n*8 + 2*t4;
            float4 v = acc[m][n];
            if (EPI == 0) {
                float* Cf = (float*)C;
                *(float2*)(Cf + (size_t)row*ldc + col)     = make_float2(v.x, v.y);
                *(float2*)(Cf + (size_t)(row+8)*ldc + col) = make_float2(v.z, v.w);
            } else {
                uint32_t* Ch = (uint32_t*)C;
                int ph = pp_h2(col);
                Ch[(size_t)row*(ldc>>1) + ph]     = h2u(v.x, v.y);
                Ch[(size_t)(row+8)*(ldc>>1) + ph] = h2u(v.z, v.w);
            }
        }
    }
}

template<int EPI>
__global__ void __launch_bounds__(256, 2) mma_gemm(
    const __half* __restrict__ A, int lda,
    const __half* __restrict__ W,
    void* __restrict__ C, int ldc, int N, int K)
{
    gemm_body<EPI>(A, lda, W, C, ldc, K, blockIdx.y*GBM, blockIdx.x*GBN);
}

// grouped stage-2: bx 0..15 -> qc, 16..31 -> kc, 32..39 -> kr (f32 natural out)
__global__ void __launch_bounds__(256, 2) mma_gemm_s2(
    const __half* __restrict__ lat3,
    const __half* __restrict__ wqp, const __half* __restrict__ wkvp,
    float* __restrict__ qc, float* __restrict__ kc, float* __restrict__ kr)
{
    int bx = blockIdx.x;
    const __half* A; const __half* W; float* C; int ldc, n0;
    if (bx < 16)      { A = lat3;        W = wqp;  C = qc; ldc = 2048; n0 = bx*128; }
    else if (bx < 32) { A = lat3 + 512;  W = wkvp; C = kc; ldc = 2048; n0 = (bx-16)*128; }
    else              { A = lat3 + 256;  W = wkvp; C = kr; ldc = 1024; n0 = (bx-32)*128; }
    gemm_body<0>(A, 768, W, C, ldc, RR, blockIdx.y*GBM, n0);
}

// --------- build q/k: rope||up -> [B,H,S,128] fp16, pair-permuted ----------
__global__ void build_qk_kernel(const float* __restrict__ ropein, int ldr,
                                const float* __restrict__ upin, int ldu,
                                __half* __restrict__ outp, float scale)
{
    int idx = blockIdx.x * blockDim.x + threadIdx.x;   // over B*H*S*64
    if (idx >= BB*HH*SS*64) return;
    int d = idx & 63;
    int s = (idx >> 6) & (SS-1);
    int h = (idx >> 17) & (HH-1);
    int b = idx >> 21;
    const size_t rbase = (size_t)(b*SS + s)*ldr + h*64;
    const size_t ubase = (size_t)(b*SS + s)*ldu + h*64;
    float x1 = ropein[rbase + d];
    float rot; int fi;
    if (d < 32) { rot = -ropein[rbase + d + 32]; fi = d; }
    else        { rot =  ropein[rbase + d - 32]; fi = d - 32; }
    float inv = __powf(10000.0f, -(float)(2*fi) * (1.0f/64.0f));
    float ang = (float)s * inv;
    float sn, cs; sincosf(ang, &sn, &cs);
    float val = fmaf(x1, cs, rot*sn);
    const int ob = ((b*HH + h)*SS + s)*128;
    const int dp = pp_el(d);
    outp[ob + dp]      = __float2half_rn(val * scale);
    outp[ob + 64 + dp] = __float2half_rn(upin[ubase + d] * scale);
}

// --------- build Vt: [bh][d][s] fp16, s pair-permuted ----------------------
__global__ void build_vt_kernel(const float* __restrict__ vf, int ldv,
                                __half* __restrict__ vt)
{
    __shared__ float tile[32][33];
    const int bh = blockIdx.z, h = bh & 15, b = bh >> 4;
    const int d0 = blockIdx.x * 32, s0 = blockIdx.y * 32;
    const int tx = threadIdx.x, ty = threadIdx.y;
    #pragma unroll
    for (int i = 0; i < 4; i++) {
        int sl = ty + i*8;
        tile[sl][tx] = vf[(size_t)(b*SS + s0 + sl)*ldv + h*64 + d0 + tx];
    }
    __syncthreads();
    const int sp = pp_el(tx);
    #pragma unroll
    for (int i = 0; i < 4; i++) {
        int dl = ty + i*8;
        vt[((size_t)bh*64 + d0 + dl)*SS + s0 + sp] = __float2half_rn(tile[tx][dl]);
    }
}

// ---------------- causal flash attention, fp16 mma, cp.async ----------------
// Q,K: [B,H,S,128] fp16 pair-perm (Q pre-scaled by log2e/sqrt(128));
// Vt: [bh][64][S] fp16 s-perm. CTA: 64 q-rows; 4 warps, each 16 rows x 64 cols.
// Q fragments + P entirely in registers; K double-buffered; V single-buffered.
#define ATQ 64
#define ATK 64
#define KH2 72      // K/Q row stride in half2 units (64 data + 8 pad)
#define VH2 40      // V row stride in half2 units (32 data + 8 pad)
#define ATTN_SMEM ((2*ATK*KH2 + 64*VH2) * 4)

__global__ void __launch_bounds__(128) attn_mma(
    const __half* __restrict__ Q, const __half* __restrict__ Kg,
    const __half* __restrict__ Vtg, __half* __restrict__ Y)
{
    extern __shared__ __align__(16) uint32_t smu[];
    uint32_t* Ks = smu;                    // [2][64][KH2]
    uint32_t* Vt = Ks + 2*ATK*KH2;         // [64][VH2]

    const int tid = threadIdx.x;
    const int lane = tid & 31, wid = tid >> 5;
    const int g = lane >> 2, t4 = lane & 3;
    const int r0 = wid*16 + g;
    const int q0 = ((int)gridDim.x - 1 - (int)blockIdx.x) * ATQ;  // heavy first
    const int bh = blockIdx.y, b = bh >> 4, h = bh & 15;

    const __half* qbase  = Q + ((size_t)bh*SS + q0)*128;
    const __half* kbase  = Kg + (size_t)bh*SS*128;
    const __half* vtbase = Vtg + (size_t)bh*64*SS;

    // prologue: Q tile -> Ks buffer 1, K(0) -> buffer 0
    uint32_t* Qstage = Ks + ATK*KH2;
    #pragma unroll
    for (int idx = tid; idx < ATQ*16; idx += 128) {
        int row = idx >> 4, seg = idx & 15;
        cp16(Qstage + row*KH2 + seg*4, qbase + row*128 + seg*8);
    }
    CP_COMMIT();                                         // group: Q
    #pragma unroll
    for (int idx = tid; idx < ATK*16; idx += 128) {
        int row = idx >> 4, seg = idx & 15;
        cp16(Ks + row*KH2 + seg*4, kbase + (size_t)row*128 + seg*8);
    }
    CP_COMMIT();                                         // group: K(0)
    CP_WAIT(1);                                          // Q ready
    __syncthreads();

    // Q fragments -> registers (8 k16-groups x 4 half2 regs)
    uint32_t qf[8][4];
    #pragma unroll
    for (int i = 0; i < 8; i++) {
        uint2 lo = *(const uint2*)(Qstage + r0*KH2 + i*8 + 2*t4);
        uint2 hi = *(const uint2*)(Qstage + (r0+8)*KH2 + i*8 + 2*t4);
        qf[i][0] = lo.x; qf[i][1] = hi.x; qf[i][2] = lo.y; qf[i][3] = hi.y;
    }

    float4 oacc[8];
    #pragma unroll
    for (int j = 0; j < 8; j++) oacc[j] = make_float4(0.f,0.f,0.f,0.f);
    float m0r = -1e30f, m1r = -1e30f, l0r = 0.f, l1r = 0.f;

    const int ntiles = q0/ATK + 1;

    for (int t = 0; t < ntiles; t++) {
        __syncthreads();          // B1: V(t-1) consumed; Qstage reads done (t=0)

        // issue V(t) into the single V buffer
        #pragma unroll
        for (int idx = tid; idx < 64*8; idx += 128) {
            int row = idx >> 3, seg = idx & 7;
            cp16(Vt + row*VH2 + seg*4, vtbase + (size_t)row*SS + t*ATK + seg*8);
        }
        CP_COMMIT();                                     // group: V(t)
        if (t + 1 < ntiles) {
            int k0n = (t+1)*ATK;
            uint32_t* Kd = Ks + ((t+1)&1)*ATK*KH2;
            #pragma unroll
            for (int idx = tid; idx < ATK*16; idx += 128) {
                int row = idx >> 4, seg = idx & 15;
                cp16(Kd + row*KH2 + seg*4, kbase + (size_t)(k0n+row)*128 + seg*8);
            }
            CP_COMMIT();                                 // group: K(t+1)
            CP_WAIT(2);                                  // K(t) ready
        } else {
            CP_WAIT(1);                                  // K(t) ready
        }
        __syncthreads();          // B2: K(t) visible

        const int k0 = t*ATK;
        const uint32_t* Kb = Ks + (t&1)*ATK*KH2;

        // ---- S = Q @ K^T : warp computes 16 rows x 64 cols ----
        float4 sf[8];
        #pragma unroll
        for (int j = 0; j < 8; j++) sf[j] = make_float4(0.f,0.f,0.f,0.f);

        #pragma unroll
        for (int i = 0; i < 8; i++) {
            #pragma unroll
            for (int j = 0; j < 8; j++) {
                uint2 bv = *(const uint2*)(Kb + (j*8+g)*KH2 + i*8 + 2*t4);
                mma_f16(sf[j], qf[i], (const uint32_t*)&bv);
            }
        }

        // ---- causal mask ----
        if (k0 + ATK - 1 > q0 + wid*16) {
            const int qr0 = q0 + r0, qr1 = qr0 + 8;
            #pragma unroll
            for (int j = 0; j < 8; j++) {
                int c0 = k0 + j*8 + 2*t4, c1 = c0 + 1;
                if (c0 > qr0) sf[j].x = -1e30f;
                if (c1 > qr0) sf[j].y = -1e30f;
                if (c0 > qr1) sf[j].z = -1e30f;
                if (c1 > qr1) sf[j].w = -1e30f;
            }
        }

        // ---- warp-local online softmax (base-2) ----
        float mx0 = -1e30f, mx1 = -1e30f;
        #pragma unroll
        for (int j = 0; j < 8; j++) {
            mx0 = fmaxf(mx0, fmaxf(sf[j].x, sf[j].y));
            mx1 = fmaxf(mx1, fmaxf(sf[j].z, sf[j].w));
        }
        mx0 = fmaxf(mx0, __shfl_xor_sync(0xffffffffu, mx0, 1));
        mx0 = fmaxf(mx0, __shfl_xor_sync(0xffffffffu, mx0, 2));
        mx1 = fmaxf(mx1, __shfl_xor_sync(0xffffffffu, mx1, 1));
        mx1 = fmaxf(mx1, __shfl_xor_sync(0xffffffffu, mx1, 2));

        float mn0 = fmaxf(m0r, mx0), mn1 = fmaxf(m1r, mx1);
        float al0 = ex2f(m0r - mn0), al1 = ex2f(m1r - mn1);
        float s0 = 0.f, s1 = 0.f;
        #pragma unroll
        for (int j = 0; j < 8; j++) {
            sf[j].x = ex2f(sf[j].x - mn0); s0 += sf[j].x;
            sf[j].y = ex2f(sf[j].y - mn0); s0 += sf[j].y;
            sf[j].z = ex2f(sf[j].z - mn1); s1 += sf[j].z;
            sf[j].w = ex2f(sf[j].w - mn1); s1 += sf[j].w;
        }
        s0 += __shfl_xor_sync(0xffffffffu, s0, 1);
        s0 += __shfl_xor_sync(0xffffffffu, s0, 2);
        s1 += __shfl_xor_sync(0xffffffffu, s1, 1);
        s1 += __shfl_xor_sync(0xffffffffu, s1, 2);
        l0r = l0r*al0 + s0;  m0r = mn0;
        l1r = l1r*al1 + s1;  m1r = mn1;

        #pragma unroll
        for (int j = 0; j < 8; j++) {
            oacc[j].x *= al0; oacc[j].y *= al0;
            oacc[j].z *= al1; oacc[j].w *= al1;
        }

        // ---- P fragments directly in registers (fp16) ----
        uint32_t pf[4][4];
        #pragma unroll
        for (int j2 = 0; j2 < 4; j2++) {
            pf[j2][0] = h2u(sf[2*j2].x,   sf[2*j2].y);     // row r0,  k pair t4
            pf[j2][1] = h2u(sf[2*j2].z,   sf[2*j2].w);     // row r0+8
            pf[j2][2] = h2u(sf[2*j2+1].x, sf[2*j2+1].y);   // row r0,  k pair t4+4
            pf[j2][3] = h2u(sf[2*j2+1].z, sf[2*j2+1].w);   // row r0+8
        }

        // ---- wait V(t), then O += P @ V ----
        if (t + 1 < ntiles) CP_WAIT(1); else CP_WAIT(0);
        __syncthreads();          // B3: V(t) visible

        #pragma unroll
        for (int j2 = 0; j2 < 4; j2++) {
            #pragma unroll
            for (int j = 0; j < 8; j++) {
                uint2 bv = *(const uint2*)(Vt + (j*8+g)*VH2 + j2*8 + 2*t4);
                mma_f16(oacc[j], pf[j2], (const uint32_t*)&bv);
            }
        }
    }

    // ---- normalize + write Y (fp16 perm-packed) ----
    const float i0 = 1.f / l0r, i1 = 1.f / l1r;
    const int row0 = q0 + r0;
    uint32_t* Yh = (uint32_t*)Y;
    #pragma unroll
    for (int j = 0; j < 8; j++) {
        int c = h*64 + j*8 + 2*t4;
        int ph = pp_h2(c);
        Yh[((size_t)b*SS + row0)*512 + ph]     = h2u(oacc[j].x*i0, oacc[j].y*i0);
        Yh[((size_t)b*SS + row0 + 8)*512 + ph] = h2u(oacc[j].z*i1, oacc[j].w*i1);
    }
}

// ---------------- host launcher --------------------------------------------
extern "C" void kernel_launch(void* const* d_in, const int* in_sizes, int n_in,
                              void* d_out, int out_size)
{
    const float* x       = (const float*)d_in[0];
    const float* wq_down = (const float*)d_in[1];
    const float* wk_rope = (const float*)d_in[2];
    const float* wkv_down= (const float*)d_in[3];
    const float* wq_rope = (const float*)d_in[4];
    const float* wq_up   = (const float*)d_in[5];
    const float* wk_up   = (const float*)d_in[6];
    const float* wv_up   = (const float*)d_in[7];
    const float* wo      = (const float*)d_in[8];
    float* out = (float*)d_out;

    static __half *p_xh=nullptr,*p_w768=nullptr,*p_wqp=nullptr,*p_wkvp=nullptr,*p_woh=nullptr,
                  *p_lat3=nullptr,*p_q=nullptr,*p_k=nullptr,*p_vt=nullptr,*p_y=nullptr;
    static float *p_qc=nullptr,*p_kc=nullptr,*p_kr=nullptr;
    static bool inited = false;
    if (!inited) {
        cudaGetSymbolAddress((void**)&p_xh,   g_xh);
        cudaGetSymbolAddress((void**)&p_w768, g_w768);
        cudaGetSymbolAddress((void**)&p_wqp,  g_wqp);
        cudaGetSymbolAddress((void**)&p_wkvp, g_wkvp);
        cudaGetSymbolAddress((void**)&p_woh,  g_woh);
        cudaGetSymbolAddress((void**)&p_lat3, g_lat3);
        cudaGetSymbolAddress((void**)&p_qc,   g_qc);
        cudaGetSymbolAddress((void**)&p_kc,   g_kc);
        cudaGetSymbolAddress((void**)&p_kr,   g_kr);
        cudaGetSymbolAddress((void**)&p_q,    g_q);
        cudaGetSymbolAddress((void**)&p_k,    g_k);
        cudaGetSymbolAddress((void**)&p_vt,   g_vt);
        cudaGetSymbolAddress((void**)&p_y,    g_y);
        cudaFuncSetAttribute(attn_mma,
            cudaFuncAttributeMaxDynamicSharedMemorySize, (int)ATTN_SMEM);
        cudaFuncSetAttribute(mma_gemm<0>,
            cudaFuncAttributeMaxDynamicSharedMemorySize, (int)GEMM_SMEM);
        cudaFuncSetAttribute(mma_gemm<1>,
            cudaFuncAttributeMaxDynamicSharedMemorySize, (int)GEMM_SMEM);
        cudaFuncSetAttribute(mma_gemm_s2,
            cudaFuncAttributeMaxDynamicSharedMemorySize, (int)GEMM_SMEM);
        inited = true;
    }

    // stage 0: fused fp16 conversion + pair-perm packing (one launch)
    cvt_all_kernel<<<(1769472 + 255)/256, 256>>>(
        x, wq_down, wk_rope, wkv_down, wq_rope, wq_up, wk_up, wv_up, wo,
        p_xh, p_w768, p_wqp, p_wkvp, p_woh);

    // stage 1: fused down projections -> lat3 (fp16 perm-packed)
    mma_gemm<1><<<dim3(768/GBN, MM/GBM), 256, GEMM_SMEM>>>(
        p_xh, EE, p_w768, p_lat3, 768, 768, EE);

    // stage 2: grouped up projections (qc | kc | kr), f32 natural out
    mma_gemm_s2<<<dim3(40, MM/GBM), 256, GEMM_SMEM>>>(
        p_lat3, p_wqp, p_wkvp, p_qc, p_kc, p_kr);

    // stage 3: head layout + RoPE -> fp16 pair-permuted q/k/vt
    int nb = (BB*HH*SS*64 + 255) / 256;
    build_qk_kernel<<<nb, 256>>>(p_qc, 2048, p_qc + 1024, 2048, p_q,
                                 0.08838834764831845f * 1.4426950408889634f);
    build_qk_kernel<<<nb, 256>>>(p_kr, 1024, p_kc,        2048, p_k, 1.0f);
    build_vt_kernel<<<dim3(2, SS/32, BB*HH), dim3(32, 8)>>>(p_kc + 1024, 2048, p_vt);

    // stage 4: causal flash attention (fp16 tensor cores)
    attn_mma<<<dim3(SS/ATQ, BB*HH), 128, ATTN_SMEM>>>(p_q, p_k, p_vt, p_y);

    // stage 5: output projection (f32 natural out)
    mma_gemm<0><<<dim3(EE/GBN, MM/GBM), 256, GEMM_SMEM>>>(
        p_y, EE, p_woh, out, EE, EE, EE);
}